// round 13
// baseline (speedup 1.0000x reference)
#include <cuda_runtime.h>
#include <cuda_fp16.h>
#include <cstdint>
#include <math.h>

// ---------------- dims ------------------------------------------------------
#define B_SZ 128
#define L_SZ 16
#define N_SZ 20000
#define HIN  512
#define H_SZ 1024
#define G4   4096
#define ML   2048
#define KSPLIT 4
// split-K chunks: 5024,5024,5024,4928 (all %32==0, sum 20000)

// ---------------- device global scratch ------------------------------------
__device__ __half g_wd[(size_t)HIN * N_SZ];       // W_down rounded fp16
__device__ float g_split[KSPLIT * ML * HIN];
__device__ __half g_vdh[ML * HIN];                // vd split
__device__ __half g_vdl[ML * HIN];
__device__ __half g_wvt[HIN * HIN];               // W_vt[:, :512] rounded
__device__ __half g_ih[ML * HIN];                 // inputs (hi, exact round)
__device__ __half g_wih[G4 * HIN];                // W_ih permuted rounded
__device__ __half g_whh[(size_t)G4 * H_SZ];       // W_hh permuted rounded
__device__ float g_xg[(size_t)ML * G4];           // permuted gate cols
__device__ __half g_hh[2 * B_SZ * H_SZ];          // h split, double buffered
__device__ __half g_hl[2 * B_SZ * H_SZ];
__device__ float g_h[B_SZ * H_SZ];
__device__ float g_c[B_SZ * H_SZ];
__device__ float g_u[HIN];
__device__ float g_ub[HIN];
__device__ float g_biasp[G4];
__device__ unsigned g_flags[256];                 // LSTM barrier flags (1/CTA)

// ---------------- helpers ---------------------------------------------------
__device__ __forceinline__ uint32_t smem_u32(const void* p) {
    uint32_t a;
    asm("{ .reg .u64 t; cvta.to.shared.u64 t, %1; cvt.u32.u64 %0, t; }" : "=r"(a) : "l"(p));
    return a;
}
__device__ __forceinline__ void cp_async16(uint32_t dst, const void* src) {
    asm volatile("cp.async.cg.shared.global [%0], [%1], 16;" :: "r"(dst), "l"(src));
}
__device__ __forceinline__ void cp_commit() {
    asm volatile("cp.async.commit_group;" ::: "memory");
}
__device__ __forceinline__ void cp_wait1() {
    asm volatile("cp.async.wait_group 1;" ::: "memory");
}
__device__ __forceinline__ void cp_wait2() {
    asm volatile("cp.async.wait_group 2;" ::: "memory");
}
__device__ __forceinline__ void ldsm4(uint32_t* r, uint32_t addr) {
    asm volatile("ldmatrix.sync.aligned.m8n8.x4.shared.b16 {%0,%1,%2,%3}, [%4];"
        : "=r"(r[0]), "=r"(r[1]), "=r"(r[2]), "=r"(r[3]) : "r"(addr));
}
__device__ __forceinline__ void mma16816(float* c, const uint32_t* a, const uint32_t* b) {
    asm volatile("mma.sync.aligned.m16n8k16.row.col.f32.f16.f16.f32 "
        "{%0,%1,%2,%3}, {%4,%5,%6,%7}, {%8,%9}, {%0,%1,%2,%3};"
        : "+f"(c[0]), "+f"(c[1]), "+f"(c[2]), "+f"(c[3])
        : "r"(a[0]), "r"(a[1]), "r"(a[2]), "r"(a[3]), "r"(b[0]), "r"(b[1]));
}
__device__ __forceinline__ float sigf(float x) { return 1.f / (1.f + expf(-x)); }
__device__ __forceinline__ void split_h(float x, __half& hi, __half& lo) {
    hi = __float2half_rn(x);
    lo = __float2half_rn(x - __half2float(hi));
}
__device__ __forceinline__ uint32_t pack2(float a, float b) {
    __half2 t; t.x = __float2half_rn(a); t.y = __float2half_rn(b);
    return *reinterpret_cast<uint32_t*>(&t);
}

// fp16 smem tile (64B rows):  16B chunk c of row r at r*64 + ((c*16) ^ (((r>>1)&3)<<4))
// fp16 smem tile (128B rows): 16B chunk c of row r at r*128 + ((c ^ (r&7))<<4)

// ---------------- GEMM1: LDG->reg fp32, convert->fp16 STS, 1-term HMMA ------
__global__ void __launch_bounds__(256, 2)
gemm1_fused(const float* __restrict__ Afp, int lda,
            const __half* __restrict__ Bm, int ldb,
            float* __restrict__ C, int ldc, size_t zstride)
{
    constexpr int BM = 128, BN = 128, WM = 64, WN = 32, MF = 4, NF = 4;
    constexpr int B16S = 128 * 64;                 // 8192 per B stage
    constexpr int OFF_AH = 3 * B16S;               // 24576; Ah[2] -> 40960 pipeline

    extern __shared__ char smem[];
    const uint32_t sbase = smem_u32(smem);
    const int tid  = threadIdx.x;
    const int lane = tid & 31;
    const int warp = tid >> 5;
    const int wm0 = (warp / (BN / WN)) * WM;
    const int wn0 = (warp % (BN / WN)) * WN;
    const int m0 = blockIdx.y * BM;
    const int n0 = blockIdx.x * BN;
    const int kbase = blockIdx.z * 5024;
    const int Kz = (blockIdx.z == 3) ? 4928 : 5024;
    C += (size_t)blockIdx.z * zstride;

    float acc[MF][NF][4];
    #pragma unroll
    for (int i = 0; i < MF; i++)
        #pragma unroll
        for (int j = 0; j < NF; j++)
            #pragma unroll
            for (int q = 0; q < 4; q++) acc[i][j][q] = 0.f;

    auto loadB = [&](int kt) {
        const int k0 = kbase + kt * 32;
        const uint32_t tb = sbase + (kt % 3) * B16S;
        #pragma unroll
        for (int q = 0; q < 2; q++) {
            const int i = tid + q * 256;
            int row = i >> 2, c = i & 3;
            uint32_t dst = tb + row * 64 + ((c * 16) ^ (((row >> 1) & 3) << 4));
            cp_async16(dst, Bm + (size_t)(n0 + row) * ldb + k0 + c * 8);
        }
    };

    float4 pa[4];
    auto ldga = [&](int kt) {
        const int k0 = kbase + kt * 32;
        #pragma unroll
        for (int q = 0; q < 4; q++) {
            const int i = tid + q * 256;
            int row = i >> 3, c = i & 7;
            pa[q] = *reinterpret_cast<const float4*>(
                Afp + (size_t)(m0 + row) * lda + k0 + c * 4);
        }
    };
    auto convert = [&](int kt) {
        char* ahb = smem + OFF_AH + (kt & 1) * 8192;
        #pragma unroll
        for (int q = 0; q < 4; q++) {
            const int i = tid + q * 256;
            int row = i >> 3, c = i & 7;
            uint2 p;
            p.x = pack2(pa[q].x, pa[q].y);
            p.y = pack2(pa[q].z, pa[q].w);
            uint32_t so = row * 64 + (((c >> 1) * 16) ^ (((row >> 1) & 3) << 4)) + (c & 1) * 8;
            *reinterpret_cast<uint2*>(ahb + so) = p;
        }
    };

    const int KT = Kz >> 5;
    loadB(0); cp_commit();
    loadB(1); cp_commit();
    ldga(0);
    convert(0);
    ldga(1);

    const int li  = lane & 15;
    const int khb = (lane >> 4) << 4;
    const int swz = ((li >> 1) & 3) << 4;

    for (int kt = 0; kt < KT; kt++) {
        if (kt + 2 < KT) loadB(kt + 2);
        cp_commit();
        cp_wait1();
        __syncthreads();

        if (kt + 1 < KT) {
            convert(kt + 1);
            if (kt + 2 < KT) ldga(kt + 2);
        }

        {
            const uint32_t tAh = sbase + OFF_AH + (kt & 1) * 8192;
            const uint32_t tB  = sbase + (kt % 3) * B16S;
            #pragma unroll
            for (int kk = 0; kk < 2; kk++) {
                const int cb = kk * 32;
                const uint32_t coff = (uint32_t)((cb + khb) ^ swz);
                uint32_t ah[MF][4];
                #pragma unroll
                for (int mf = 0; mf < MF; mf++) {
                    uint32_t ro = (wm0 + mf * 16 + li) * 64 + coff;
                    ldsm4(ah[mf], tAh + ro);
                }
                uint32_t bh[NF][2];
                #pragma unroll
                for (int nf2 = 0; nf2 < NF / 2; nf2++) {
                    uint32_t ro = (wn0 + nf2 * 16 + li) * 64 + coff;
                    uint32_t t[4];
                    ldsm4(t, tB + ro);
                    bh[2 * nf2][0] = t[0]; bh[2 * nf2][1] = t[2];
                    bh[2 * nf2 + 1][0] = t[1]; bh[2 * nf2 + 1][1] = t[3];
                }
                #pragma unroll
                for (int mf = 0; mf < MF; mf++)
                    #pragma unroll
                    for (int nf = 0; nf < NF; nf++)
                        mma16816(acc[mf][nf], ah[mf], bh[nf]);
            }
        }
        __syncthreads();
    }

    float* st = reinterpret_cast<float*>(smem) + warp * (WM * 33);
    #pragma unroll
    for (int mf = 0; mf < MF; mf++)
        #pragma unroll
        for (int nf = 0; nf < NF; nf++)
            #pragma unroll
            for (int i = 0; i < 2; i++) {
                int r = mf * 16 + (lane >> 2) + 8 * i;
                int c = nf * 8 + 2 * (lane & 3);
                st[r * 33 + c]     = acc[mf][nf][2 * i];
                st[r * 33 + c + 1] = acc[mf][nf][2 * i + 1];
            }
    __syncwarp();
    #pragma unroll
    for (int rr = lane; rr < WM; rr += 32) {
        const int m = m0 + wm0 + rr;
        #pragma unroll
        for (int c4 = 0; c4 < WN; c4 += 4) {
            float4 v;
            v.x = st[rr * 33 + c4];     v.y = st[rr * 33 + c4 + 1];
            v.z = st[rr * 33 + c4 + 2]; v.w = st[rr * 33 + c4 + 3];
            *reinterpret_cast<float4*>(C + (size_t)m * ldc + n0 + wn0 + c4) = v;
        }
    }
}

// ---------------- generic fp16 GEMM (modes 1,2; 1 or 2 A terms) -------------
template<int BM, int BN, int WM, int WN, int MODE, int TERMS>
__global__ void __launch_bounds__((BM / WM) * (BN / WN) * 32)
mma_gemm(const __half* __restrict__ Ah, const __half* __restrict__ Al, int lda,
         const __half* __restrict__ Bm, int ldb, int K,
         float* __restrict__ C, int ldc,
         const float* __restrict__ bias,
         const float* __restrict__ srow, const float* __restrict__ ucol,
         __half* __restrict__ Ch)
{
    constexpr int NT = (BM / WM) * (BN / WN) * 32;
    constexpr int MF = WM / 16;
    constexpr int NF = WN / 8;
    constexpr int STAGE = (TERMS * BM + BN) * 64;
    constexpr int CHA = BM * 4;
    constexpr int CHB = BN * 4;
    constexpr int CHT = TERMS * CHA + CHB;

    extern __shared__ char smem[];
    const uint32_t sbase = smem_u32(smem);
    const int tid  = threadIdx.x;
    const int lane = tid & 31;
    const int warp = tid >> 5;
    const int wm0 = (warp / (BN / WN)) * WM;
    const int wn0 = (warp % (BN / WN)) * WN;
    const int m0 = blockIdx.y * BM;
    const int n0 = blockIdx.x * BN;

    float acc[MF][NF][4];
    #pragma unroll
    for (int i = 0; i < MF; i++)
        #pragma unroll
        for (int j = 0; j < NF; j++)
            #pragma unroll
            for (int q = 0; q < 4; q++) acc[i][j][q] = 0.f;

    auto load_stage = [&](int kt, int s) {
        const int k0 = kt * 32;
        const uint32_t tb = sbase + s * STAGE;
        #pragma unroll
        for (int q = 0; q < CHT / NT; q++) {
            const int i = tid + q * NT;
            const __half* src;
            int toff, rr;
            if (i < CHA) {
                rr = i >> 2; src = Ah + (size_t)(m0 + rr) * lda; toff = 0;
            } else if (TERMS == 2 && i < 2 * CHA) {
                int j = i - CHA; rr = j >> 2;
                src = Al + (size_t)(m0 + rr) * lda; toff = BM * 64;
            } else {
                int j = i - TERMS * CHA; rr = j >> 2;
                src = Bm + (size_t)(n0 + rr) * ldb; toff = TERMS * BM * 64;
            }
            const int c = i & 3;
            uint32_t dst = tb + toff + rr * 64 + ((c * 16) ^ (((rr >> 1) & 3) << 4));
            cp_async16(dst, src + k0 + c * 8);
        }
    };

    const int KT = K >> 5;
    load_stage(0, 0); cp_commit();
    load_stage(1, 1); cp_commit();

    const int li  = lane & 15;
    const int khb = (lane >> 4) << 4;
    const int swz = ((li >> 1) & 3) << 4;

    for (int kt = 0; kt < KT; kt++) {
        const int s = kt % 3;
        if (kt + 2 < KT) load_stage(kt + 2, (kt + 2) % 3);
        cp_commit();
        cp_wait2();
        __syncthreads();

        const uint32_t tA  = sbase + s * STAGE;
        const uint32_t tAl = tA + BM * 64;
        const uint32_t tB  = tA + TERMS * BM * 64;

        #pragma unroll
        for (int kk = 0; kk < 2; kk++) {
            const int cb = kk * 32;
            const uint32_t coff = (uint32_t)((cb + khb) ^ swz);
            uint32_t ah[MF][4], al_[MF][4];
            #pragma unroll
            for (int mf = 0; mf < MF; mf++) {
                uint32_t ro = (wm0 + mf * 16 + li) * 64 + coff;
                ldsm4(ah[mf], tA + ro);
                if (TERMS == 2) ldsm4(al_[mf], tAl + ro);
            }
            uint32_t bh[NF][2];
            #pragma unroll
            for (int nf2 = 0; nf2 < NF / 2; nf2++) {
                uint32_t ro = (wn0 + nf2 * 16 + li) * 64 + coff;
                uint32_t t[4];
                ldsm4(t, tB + ro);
                bh[2 * nf2][0] = t[0]; bh[2 * nf2][1] = t[2];
                bh[2 * nf2 + 1][0] = t[1]; bh[2 * nf2 + 1][1] = t[3];
            }
            #pragma unroll
            for (int mf = 0; mf < MF; mf++)
                #pragma unroll
                for (int nf = 0; nf < NF; nf++) {
                    mma16816(acc[mf][nf], ah[mf], bh[nf]);
                    if (TERMS == 2) mma16816(acc[mf][nf], al_[mf], bh[nf]);
                }
        }
        __syncthreads();
    }

    float* st = reinterpret_cast<float*>(smem) + warp * (WM * 33);
    #pragma unroll
    for (int mf = 0; mf < MF; mf++)
        #pragma unroll
        for (int nf = 0; nf < NF; nf++)
            #pragma unroll
            for (int i = 0; i < 2; i++) {
                int r = mf * 16 + (lane >> 2) + 8 * i;
                int c = nf * 8 + 2 * (lane & 3);
                st[r * 33 + c]     = acc[mf][nf][2 * i];
                st[r * 33 + c + 1] = acc[mf][nf][2 * i + 1];
            }
    __syncwarp();
    #pragma unroll
    for (int rr = lane; rr < WM; rr += 32) {
        const int m = m0 + wm0 + rr;
        const int nbase = n0 + wn0;
        if (MODE == 1) {
            const float tm = srow[m];
            #pragma unroll
            for (int c = 0; c < WN; c += 2) {
                int n = nbase + c;
                float v0 = st[rr * 33 + c]     + tm * ucol[n]     + bias[n];
                float v1 = st[rr * 33 + c + 1] + tm * ucol[n + 1] + bias[n + 1];
                __half2 ph;
                ph.x = __float2half_rn(v0); ph.y = __float2half_rn(v1);
                *reinterpret_cast<__half2*>(Ch + (size_t)m * ldc + n) = ph;
            }
        } else {
            #pragma unroll
            for (int c4 = 0; c4 < WN; c4 += 4) {
                float4 v;
                v.x = st[rr * 33 + c4];
                v.y = st[rr * 33 + c4 + 1];
                v.z = st[rr * 33 + c4 + 2];
                v.w = st[rr * 33 + c4 + 3];
                int n = nbase + c4;
                v.x += bias[n]; v.y += bias[n + 1];
                v.z += bias[n + 2]; v.w += bias[n + 3];
                *reinterpret_cast<float4*>(C + (size_t)m * ldc + nbase + c4) = v;
            }
        }
    }
}

// ---------------- persistent fused LSTM, BK=64, flag barrier -----------------
__global__ void __launch_bounds__(128)
lstm_persist(const __half* __restrict__ hhb, const __half* __restrict__ hlb,
             const __half* __restrict__ Bm,
             const float* __restrict__ xg, float* __restrict__ cstate,
             float* __restrict__ houtf,
             __half* __restrict__ hhw, __half* __restrict__ hlw)
{
    constexpr int BM = 32, BN = 64, NT = 128, NF = 4;
    constexpr int STAGE = (2 * BM + BN) * 128;   // 16384
    constexpr int CHA = BM * 8, CHB = BN * 8, CHT = 2 * CHA + CHB;

    extern __shared__ char smem[];
    const uint32_t sbase = smem_u32(smem);
    const int tid  = threadIdx.x;
    const int lane = tid & 31;
    const int warp = tid >> 5;
    const int wm0 = (warp >> 1) * 16;
    const int wn0 = (warp & 1) * 32;
    const int m0 = blockIdx.y * BM;
    const int n0 = blockIdx.x * BN;
    const int li  = lane & 15;
    const int qhb = lane >> 4;
    const int cta = blockIdx.y * 64 + blockIdx.x;   // 0..255

    // spread-flag device barrier: arrival = 1 store; wait = spread polls
    auto dev_barrier = [&](unsigned sv) {
        __threadfence();
        __syncthreads();
        if (tid == 0) ((volatile unsigned*)g_flags)[cta] = sv;
        volatile unsigned* vf = g_flags;
        #pragma unroll
        for (int f = 0; f < 2; f++) {
            int idx = tid + f * 128;
            while (vf[idx] < sv) { }
        }
        __syncthreads();
    };

    // ---- step 0: h=c=0, gates = xg row ----
    {
        __half* Oh = hhw;
        __half* Ol = hlw;
        const float* xgl = xg;
        #pragma unroll
        for (int qsel = 0; qsel < NF / 2; qsel++) {
            const int nb = n0 + wn0 + qsel * 16;
            const int a  = lane & 3;
            const int j  = 4 * (nb >> 4) + a;
            #pragma unroll
            for (int i = 0; i < 2; i++) {
                const int m = m0 + wm0 + (lane >> 2) + 8 * i;
                const float* xrow = xgl + (size_t)m * (L_SZ * G4);
                float2 xif = *reinterpret_cast<const float2*>(xrow + nb + 2 * a);
                float2 xgo = *reinterpret_cast<const float2*>(xrow + nb + 8 + 2 * a);
                float ig = sigf(xif.x);
                float gg = tanhf(xgo.x), og = sigf(xgo.y);
                const int gi = (m << 10) + j;
                float cv = ig * gg;
                cstate[gi] = cv;
                float hv = og * tanhf(cv);
                __half hi, lo; split_h(hv, hi, lo);
                Oh[gi] = hi; Ol[gi] = lo;
            }
        }
        dev_barrier(1u);
    }

    for (int l = 1; l < L_SZ; l++) {
        const __half* Ah = hhb + (size_t)((l + 1) & 1) * (B_SZ * H_SZ);
        const __half* Al = hlb + (size_t)((l + 1) & 1) * (B_SZ * H_SZ);
        __half* Oh = hhw + (size_t)(l & 1) * (B_SZ * H_SZ);
        __half* Ol = hlw + (size_t)(l & 1) * (B_SZ * H_SZ);
        const float* xgl = xg + (size_t)l * G4;

        float acc[NF][4];
        #pragma unroll
        for (int j = 0; j < NF; j++)
            #pragma unroll
            for (int q = 0; q < 4; q++) acc[j][q] = 0.f;

        auto load_stage = [&](int kt, int s) {
            const int k0 = kt * 64;
            const uint32_t tb = sbase + s * STAGE;
            #pragma unroll
            for (int q = 0; q < CHT / NT; q++) {
                const int i = tid + q * NT;
                const __half* src;
                int toff, rr;
                if (i < CHA) {
                    rr = i >> 3; src = Ah + (size_t)(m0 + rr) * H_SZ; toff = 0;
                } else if (i < 2 * CHA) {
                    int j = i - CHA; rr = j >> 3;
                    src = Al + (size_t)(m0 + rr) * H_SZ; toff = BM * 128;
                } else {
                    int j = i - 2 * CHA; rr = j >> 3;
                    src = Bm + (size_t)(n0 + rr) * H_SZ; toff = 2 * BM * 128;
                }
                const int c = i & 7;
                uint32_t dst = tb + toff + rr * 128 + ((c ^ (rr & 7)) << 4);
                cp_async16(dst, src + k0 + c * 8);
            }
        };

        const int KT = H_SZ >> 6;   // 16
        load_stage(0, 0); cp_commit();
        load_stage(1, 1); cp_commit();

        for (int kt = 0; kt < KT; kt++) {
            const int s = kt % 3;
            if (kt + 2 < KT) load_stage(kt + 2, (kt + 2) % 3);
            cp_commit();
            cp_wait2();
            __syncthreads();

            const uint32_t tA  = sbase + s * STAGE;
            const uint32_t tAl = tA + BM * 128;
            const uint32_t tB  = tA + 2 * BM * 128;

            #pragma unroll
            for (int kk = 0; kk < 4; kk++) {
                const int q = kk * 2 + qhb;
                const uint32_t sw = (uint32_t)((q ^ (li & 7)) << 4);
                uint32_t ah[4], al_[4];
                {
                    uint32_t ro = (wm0 + li) * 128 + sw;
                    ldsm4(ah,  tA  + ro);
                    ldsm4(al_, tAl + ro);
                }
                uint32_t bh[NF][2];
                #pragma unroll
                for (int nf2 = 0; nf2 < NF / 2; nf2++) {
                    uint32_t ro = (wn0 + nf2 * 16 + li) * 128 + sw;
                    uint32_t t[4];
                    ldsm4(t, tB + ro);
                    bh[2 * nf2][0] = t[0]; bh[2 * nf2][1] = t[2];
                    bh[2 * nf2 + 1][0] = t[1]; bh[2 * nf2 + 1][1] = t[3];
                }
                #pragma unroll
                for (int nf = 0; nf < NF; nf++) {
                    mma16816(acc[nf], ah,  bh[nf]);
                    mma16816(acc[nf], al_, bh[nf]);
                }
            }
            __syncthreads();
        }

        // fused gate nonlinearity + state update
        #pragma unroll
        for (int qsel = 0; qsel < NF / 2; qsel++) {
            const int nb = n0 + wn0 + qsel * 16;
            const int a  = lane & 3;
            const int j  = 4 * (nb >> 4) + a;
            #pragma unroll
            for (int i = 0; i < 2; i++) {
                const int m = m0 + wm0 + (lane >> 2) + 8 * i;
                const float* xrow = xgl + (size_t)m * (L_SZ * G4);
                float2 xif = *reinterpret_cast<const float2*>(xrow + nb + 2 * a);
                float2 xgo = *reinterpret_cast<const float2*>(xrow + nb + 8 + 2 * a);
                float xi = acc[2 * qsel][2 * i]         + xif.x;
                float xf = acc[2 * qsel][2 * i + 1]     + xif.y;
                float xgv = acc[2 * qsel + 1][2 * i]    + xgo.x;
                float xo = acc[2 * qsel + 1][2 * i + 1] + xgo.y;
                float ig = sigf(xi), fg = sigf(xf);
                float gg = tanhf(xgv), og = sigf(xo);
                const int gi = (m << 10) + j;
                float cv = fg * cstate[gi] + ig * gg;
                cstate[gi] = cv;
                float hv = og * tanhf(cv);
                houtf[gi] = hv;
                __half hi, lo; split_h(hv, hi, lo);
                Oh[gi] = hi; Ol[gi] = lo;
            }
        }

        dev_barrier((unsigned)(l + 1));
    }
}

// ---------------- converts (8 floats/thread, 16B stores) ---------------------
__global__ void conv_round(const float* __restrict__ src, int C, int srcld,
                           __half* __restrict__ dst)
{
    int c8 = (blockIdx.x * blockDim.x + threadIdx.x) * 8;
    int r = blockIdx.y;
    if (c8 >= C) return;
    float4 x0 = *reinterpret_cast<const float4*>(src + (size_t)r * srcld + c8);
    float4 x1 = *reinterpret_cast<const float4*>(src + (size_t)r * srcld + c8 + 4);
    uint4 p;
    p.x = pack2(x0.x, x0.y); p.y = pack2(x0.z, x0.w);
    p.z = pack2(x1.x, x1.y); p.w = pack2(x1.z, x1.w);
    *reinterpret_cast<uint4*>(dst + (size_t)r * C + c8) = p;
}

__global__ void conv_perm_round(const float* __restrict__ src, int cols,
                                __half* __restrict__ dst)
{
    int c8 = (blockIdx.x * blockDim.x + threadIdx.x) * 8;
    int r = blockIdx.y;
    if (c8 >= cols) return;
    int gate = ((r >> 3) & 1) * 2 + (r & 1);
    int cell = 4 * (r >> 4) + ((r >> 1) & 3);
    int orig = gate * 1024 + cell;
    float4 x0 = *reinterpret_cast<const float4*>(src + (size_t)orig * cols + c8);
    float4 x1 = *reinterpret_cast<const float4*>(src + (size_t)orig * cols + c8 + 4);
    uint4 p;
    p.x = pack2(x0.x, x0.y); p.y = pack2(x0.z, x0.w);
    p.z = pack2(x1.x, x1.y); p.w = pack2(x1.z, x1.w);
    *reinterpret_cast<uint4*>(dst + (size_t)r * cols + c8) = p;
}

__global__ void prep_kernel(const float* __restrict__ Wvt,
                            const float* __restrict__ wtw,
                            const float* __restrict__ wtb,
                            const float* __restrict__ bih,
                            const float* __restrict__ bhh)
{
    int i = blockIdx.x * blockDim.x + threadIdx.x;
    if (i < 256) g_flags[i] = 0;
    if (i < HIN) {
        const float* row = Wvt + (size_t)i * (HIN + 128) + HIN;
        float u = 0.f, ub = 0.f;
        #pragma unroll 4
        for (int j = 0; j < 128; j++) { float w = row[j]; u += w * wtw[j]; ub += w * wtb[j]; }
        g_u[i] = u; g_ub[i] = ub;
    } else if (i < HIN + G4) {
        int r = i - HIN;
        int gate = ((r >> 3) & 1) * 2 + (r & 1);
        int cell = 4 * (r >> 4) + ((r >> 1) & 3);
        g_biasp[r] = bih[gate * 1024 + cell] + bhh[gate * 1024 + cell];
    } else if (i < HIN + G4 + HIN * HIN / 8) {
        int w = i - (HIN + G4);
        int r = w >> 6;
        int c8 = (w & 63) * 8;
        float4 x0 = *reinterpret_cast<const float4*>(Wvt + (size_t)r * (HIN + 128) + c8);
        float4 x1 = *reinterpret_cast<const float4*>(Wvt + (size_t)r * (HIN + 128) + c8 + 4);
        uint4 p;
        p.x = pack2(x0.x, x0.y); p.y = pack2(x0.z, x0.w);
        p.z = pack2(x1.x, x1.y); p.w = pack2(x1.z, x1.w);
        *reinterpret_cast<uint4*>(g_wvt + (size_t)r * HIN + c8) = p;
    }
}

__global__ void reduce_conv(void)
{
    int idx = blockIdx.x * 256 + threadIdx.x;
    float s = 0.f;
    #pragma unroll
    for (int z = 0; z < KSPLIT; z++) s += g_split[(size_t)z * ML * HIN + idx];
    __half hi, lo; split_h(s, hi, lo);
    g_vdh[idx] = hi; g_vdl[idx] = lo;
}

__global__ void pred_kernel(const float* __restrict__ lw,
                            const float* __restrict__ lb,
                            float* __restrict__ out)
{
    int b = blockIdx.x, tid = threadIdx.x;
    const float* hr = g_h + (size_t)b * H_SZ;
    float s = 0.f;
    for (int k = tid; k < H_SZ; k += 128) s += hr[k] * lw[k];
    __shared__ float red[128];
    red[tid] = s; __syncthreads();
    for (int off = 64; off > 0; off >>= 1) {
        if (tid < off) red[tid] += red[tid + off];
        __syncthreads();
    }
    if (tid == 0) out[b] = red[0] + lb[0];
}

// ---------------- launch -----------------------------------------------------
#define SMEM_G1   67584                          // max(pipeline 40960, epilogue)
#define SMEM_G2   ((2 * 64 + 128) * 64 * 3)      // 49152 (BM=64 2-term)
#define SMEM_T1   67584
#define SMEM_LSTM ((2 * 32 + 64) * 128 * 3)      // 49152

extern "C" void kernel_launch(void* const* d_in, const int* in_sizes, int n_in,
                              void* d_out, int out_size)
{
    const float* v   = (const float*)d_in[0];
    const float* t   = (const float*)d_in[1];
    const float* Wd  = (const float*)d_in[2];
    const float* wtw = (const float*)d_in[3];
    const float* wtb = (const float*)d_in[4];
    const float* Wvt = (const float*)d_in[5];
    const float* Wih = (const float*)d_in[6];
    const float* Whh = (const float*)d_in[7];
    const float* bih = (const float*)d_in[8];
    const float* bhh = (const float*)d_in[9];
    const float* lw  = (const float*)d_in[10];
    const float* lb  = (const float*)d_in[11];
    float* out = (float*)d_out;

    __half *p_wd, *p_vdh, *p_vdl, *p_wvt, *p_ih, *p_wih, *p_whh, *p_hh, *p_hl;
    float *p_split, *p_xg, *p_h, *p_c, *p_u, *p_ub, *p_biasp;
    cudaGetSymbolAddress((void**)&p_wd, g_wd);
    cudaGetSymbolAddress((void**)&p_vdh, g_vdh); cudaGetSymbolAddress((void**)&p_vdl, g_vdl);
    cudaGetSymbolAddress((void**)&p_wvt, g_wvt);
    cudaGetSymbolAddress((void**)&p_ih, g_ih);
    cudaGetSymbolAddress((void**)&p_wih, g_wih); cudaGetSymbolAddress((void**)&p_whh, g_whh);
    cudaGetSymbolAddress((void**)&p_hh, g_hh);   cudaGetSymbolAddress((void**)&p_hl, g_hl);
    cudaGetSymbolAddress((void**)&p_split, g_split);
    cudaGetSymbolAddress((void**)&p_xg, g_xg);
    cudaGetSymbolAddress((void**)&p_h, g_h);     cudaGetSymbolAddress((void**)&p_c, g_c);
    cudaGetSymbolAddress((void**)&p_u, g_u);     cudaGetSymbolAddress((void**)&p_ub, g_ub);
    cudaGetSymbolAddress((void**)&p_biasp, g_biasp);

    cudaFuncSetAttribute(gemm1_fused, cudaFuncAttributeMaxDynamicSharedMemorySize, SMEM_G1);
    cudaFuncSetAttribute(mma_gemm<64, 128, 32, 32, 1, 2>, cudaFuncAttributeMaxDynamicSharedMemorySize, SMEM_G2);
    cudaFuncSetAttribute(mma_gemm<128, 128, 64, 32, 2, 1>, cudaFuncAttributeMaxDynamicSharedMemorySize, SMEM_T1);
    cudaFuncSetAttribute(lstm_persist, cudaFuncAttributeMaxDynamicSharedMemorySize, SMEM_LSTM);

    // 1) prep  2) W_down round  3) W_ih perm-round
    prep_kernel<<<(HIN + G4 + HIN * HIN / 8 + 255) / 256, 256>>>(Wvt, wtw, wtb, bih, bhh);
    conv_round<<<dim3((N_SZ / 8 + 255) / 256, HIN), 256>>>(Wd, N_SZ, N_SZ, p_wd);
    conv_perm_round<<<dim3(1, G4), 256>>>(Wih, HIN, p_wih);

    // 4) GEMM1 (LDG-reg convert, 1-term, split-K=4)
    gemm1_fused<<<dim3(HIN / 128, ML / 128, KSPLIT), 256, SMEM_G1>>>(
        v, N_SZ, p_wd, N_SZ, p_split, HIN, (size_t)ML * HIN);

    // 5) reduce partials -> vd fp16 split
    reduce_conv<<<(ML * HIN) / 256, 256>>>();

    // 6) GEMM2 (2-term, 64x128 tiles -> 128 CTAs)
    mma_gemm<64, 128, 32, 32, 1, 2><<<dim3(HIN / 128, ML / 64), 256, SMEM_G2>>>(
        p_vdh, p_vdl, HIN, p_wvt, HIN, HIN,
        nullptr, HIN, p_ub, t, p_u, p_ih);

    // 7) GEMM3 (1-term): xg = inputs_fp16 @ Wih_perm^T + bias_perm
    mma_gemm<128, 128, 64, 32, 2, 1><<<dim3(G4 / 128, ML / 128), 256, SMEM_T1>>>(
        p_ih, nullptr, HIN, p_wih, HIN, HIN,
        p_xg, G4, p_biasp, nullptr, nullptr, nullptr);

    // 8) W_hh perm-round  9) persistent LSTM steps 0..15 (flag barrier)
    conv_perm_round<<<dim3(1, G4), 256>>>(Whh, H_SZ, p_whh);
    lstm_persist<<<dim3(G4 / 64, B_SZ / 32), 128, SMEM_LSTM>>>(
        p_hh, p_hl, p_whh, p_xg, p_c, p_h, p_hh, p_hl);

    // 10) pred
    pred_kernel<<<B_SZ, 128>>>(lw, lb, out);
}

// round 14
// speedup vs baseline: 1.2828x; 1.2828x over previous
#include <cuda_runtime.h>
#include <cuda_fp16.h>
#include <cstdint>
#include <math.h>

// ---------------- dims ------------------------------------------------------
#define B_SZ 128
#define L_SZ 16
#define N_SZ 20000
#define HIN  512
#define H_SZ 1024
#define G4   4096
#define ML   2048
#define KSPLIT 4
// split-K chunks: 5024,5024,5024,4928 (all %32==0, sum 20000)

// ---------------- device global scratch ------------------------------------
__device__ __half g_wd[(size_t)HIN * N_SZ];       // W_down rounded fp16
__device__ float g_split[KSPLIT * ML * HIN];
__device__ __half g_vdh[ML * HIN];                // vd split
__device__ __half g_vdl[ML * HIN];
__device__ __half g_wvt[HIN * HIN];               // W_vt[:, :512] rounded
__device__ __half g_ih[ML * HIN];                 // inputs (hi, exact round)
__device__ __half g_wih[G4 * HIN];                // W_ih permuted rounded
__device__ __half g_whh[(size_t)G4 * H_SZ];       // W_hh permuted rounded
__device__ float g_xg[(size_t)ML * G4];           // permuted gate cols
__device__ __half g_hh[2 * B_SZ * H_SZ];          // h split, double buffered
__device__ __half g_hl[2 * B_SZ * H_SZ];
__device__ float g_h[B_SZ * H_SZ];
__device__ float g_c[B_SZ * H_SZ];
__device__ float g_u[HIN];
__device__ float g_ub[HIN];
__device__ float g_biasp[G4];
__device__ unsigned g_bar;                        // LSTM barrier counter

// ---------------- helpers ---------------------------------------------------
__device__ __forceinline__ uint32_t smem_u32(const void* p) {
    uint32_t a;
    asm("{ .reg .u64 t; cvta.to.shared.u64 t, %1; cvt.u32.u64 %0, t; }" : "=r"(a) : "l"(p));
    return a;
}
__device__ __forceinline__ void cp_async16(uint32_t dst, const void* src) {
    asm volatile("cp.async.cg.shared.global [%0], [%1], 16;" :: "r"(dst), "l"(src));
}
__device__ __forceinline__ void cp_commit() {
    asm volatile("cp.async.commit_group;" ::: "memory");
}
__device__ __forceinline__ void cp_wait1() {
    asm volatile("cp.async.wait_group 1;" ::: "memory");
}
__device__ __forceinline__ void cp_wait2() {
    asm volatile("cp.async.wait_group 2;" ::: "memory");
}
__device__ __forceinline__ void ldsm4(uint32_t* r, uint32_t addr) {
    asm volatile("ldmatrix.sync.aligned.m8n8.x4.shared.b16 {%0,%1,%2,%3}, [%4];"
        : "=r"(r[0]), "=r"(r[1]), "=r"(r[2]), "=r"(r[3]) : "r"(addr));
}
__device__ __forceinline__ void mma16816(float* c, const uint32_t* a, const uint32_t* b) {
    asm volatile("mma.sync.aligned.m16n8k16.row.col.f32.f16.f16.f32 "
        "{%0,%1,%2,%3}, {%4,%5,%6,%7}, {%8,%9}, {%0,%1,%2,%3};"
        : "+f"(c[0]), "+f"(c[1]), "+f"(c[2]), "+f"(c[3])
        : "r"(a[0]), "r"(a[1]), "r"(a[2]), "r"(a[3]), "r"(b[0]), "r"(b[1]));
}
__device__ __forceinline__ float sigf(float x) { return 1.f / (1.f + expf(-x)); }
__device__ __forceinline__ void split_h(float x, __half& hi, __half& lo) {
    hi = __float2half_rn(x);
    lo = __float2half_rn(x - __half2float(hi));
}
__device__ __forceinline__ uint32_t pack2(float a, float b) {
    __half2 t; t.x = __float2half_rn(a); t.y = __float2half_rn(b);
    return *reinterpret_cast<uint32_t*>(&t);
}

// fp16 smem tile (64B rows):  16B chunk c of row r at r*64 + ((c*16) ^ (((r>>1)&3)<<4))
// fp16 smem tile (128B rows): 16B chunk c of row r at r*128 + ((c ^ (r&7))<<4)

// ---------------- GEMM1: LDG->reg fp32, convert->fp16 STS, 1-term HMMA ------
__global__ void __launch_bounds__(256, 2)
gemm1_fused(const float* __restrict__ Afp, int lda,
            const __half* __restrict__ Bm, int ldb,
            float* __restrict__ C, int ldc, size_t zstride)
{
    constexpr int BM = 128, BN = 128, WM = 64, WN = 32, MF = 4, NF = 4;
    constexpr int B16S = 128 * 64;                 // 8192 per B stage
    constexpr int OFF_AH = 3 * B16S;               // 24576; Ah[2] -> 40960 pipeline

    extern __shared__ char smem[];
    const uint32_t sbase = smem_u32(smem);
    const int tid  = threadIdx.x;
    const int lane = tid & 31;
    const int warp = tid >> 5;
    const int wm0 = (warp / (BN / WN)) * WM;
    const int wn0 = (warp % (BN / WN)) * WN;
    const int m0 = blockIdx.y * BM;
    const int n0 = blockIdx.x * BN;
    const int kbase = blockIdx.z * 5024;
    const int Kz = (blockIdx.z == 3) ? 4928 : 5024;
    C += (size_t)blockIdx.z * zstride;

    float acc[MF][NF][4];
    #pragma unroll
    for (int i = 0; i < MF; i++)
        #pragma unroll
        for (int j = 0; j < NF; j++)
            #pragma unroll
            for (int q = 0; q < 4; q++) acc[i][j][q] = 0.f;

    auto loadB = [&](int kt) {
        const int k0 = kbase + kt * 32;
        const uint32_t tb = sbase + (kt % 3) * B16S;
        #pragma unroll
        for (int q = 0; q < 2; q++) {
            const int i = tid + q * 256;
            int row = i >> 2, c = i & 3;
            uint32_t dst = tb + row * 64 + ((c * 16) ^ (((row >> 1) & 3) << 4));
            cp_async16(dst, Bm + (size_t)(n0 + row) * ldb + k0 + c * 8);
        }
    };

    float4 pa[4];
    auto ldga = [&](int kt) {
        const int k0 = kbase + kt * 32;
        #pragma unroll
        for (int q = 0; q < 4; q++) {
            const int i = tid + q * 256;
            int row = i >> 3, c = i & 7;
            pa[q] = *reinterpret_cast<const float4*>(
                Afp + (size_t)(m0 + row) * lda + k0 + c * 4);
        }
    };
    auto convert = [&](int kt) {
        char* ahb = smem + OFF_AH + (kt & 1) * 8192;
        #pragma unroll
        for (int q = 0; q < 4; q++) {
            const int i = tid + q * 256;
            int row = i >> 3, c = i & 7;
            uint2 p;
            p.x = pack2(pa[q].x, pa[q].y);
            p.y = pack2(pa[q].z, pa[q].w);
            uint32_t so = row * 64 + (((c >> 1) * 16) ^ (((row >> 1) & 3) << 4)) + (c & 1) * 8;
            *reinterpret_cast<uint2*>(ahb + so) = p;
        }
    };

    const int KT = Kz >> 5;
    loadB(0); cp_commit();
    loadB(1); cp_commit();
    ldga(0);
    convert(0);
    ldga(1);

    const int li  = lane & 15;
    const int khb = (lane >> 4) << 4;
    const int swz = ((li >> 1) & 3) << 4;

    for (int kt = 0; kt < KT; kt++) {
        if (kt + 2 < KT) loadB(kt + 2);
        cp_commit();
        cp_wait1();
        __syncthreads();

        if (kt + 1 < KT) {
            convert(kt + 1);
            if (kt + 2 < KT) ldga(kt + 2);
        }

        {
            const uint32_t tAh = sbase + OFF_AH + (kt & 1) * 8192;
            const uint32_t tB  = sbase + (kt % 3) * B16S;
            #pragma unroll
            for (int kk = 0; kk < 2; kk++) {
                const int cb = kk * 32;
                const uint32_t coff = (uint32_t)((cb + khb) ^ swz);
                uint32_t ah[MF][4];
                #pragma unroll
                for (int mf = 0; mf < MF; mf++) {
                    uint32_t ro = (wm0 + mf * 16 + li) * 64 + coff;
                    ldsm4(ah[mf], tAh + ro);
                }
                uint32_t bh[NF][2];
                #pragma unroll
                for (int nf2 = 0; nf2 < NF / 2; nf2++) {
                    uint32_t ro = (wn0 + nf2 * 16 + li) * 64 + coff;
                    uint32_t t[4];
                    ldsm4(t, tB + ro);
                    bh[2 * nf2][0] = t[0]; bh[2 * nf2][1] = t[2];
                    bh[2 * nf2 + 1][0] = t[1]; bh[2 * nf2 + 1][1] = t[3];
                }
                #pragma unroll
                for (int mf = 0; mf < MF; mf++)
                    #pragma unroll
                    for (int nf = 0; nf < NF; nf++)
                        mma16816(acc[mf][nf], ah[mf], bh[nf]);
            }
        }
        __syncthreads();
    }

    float* st = reinterpret_cast<float*>(smem) + warp * (WM * 33);
    #pragma unroll
    for (int mf = 0; mf < MF; mf++)
        #pragma unroll
        for (int nf = 0; nf < NF; nf++)
            #pragma unroll
            for (int i = 0; i < 2; i++) {
                int r = mf * 16 + (lane >> 2) + 8 * i;
                int c = nf * 8 + 2 * (lane & 3);
                st[r * 33 + c]     = acc[mf][nf][2 * i];
                st[r * 33 + c + 1] = acc[mf][nf][2 * i + 1];
            }
    __syncwarp();
    #pragma unroll
    for (int rr = lane; rr < WM; rr += 32) {
        const int m = m0 + wm0 + rr;
        #pragma unroll
        for (int c4 = 0; c4 < WN; c4 += 4) {
            float4 v;
            v.x = st[rr * 33 + c4];     v.y = st[rr * 33 + c4 + 1];
            v.z = st[rr * 33 + c4 + 2]; v.w = st[rr * 33 + c4 + 3];
            *reinterpret_cast<float4*>(C + (size_t)m * ldc + n0 + wn0 + c4) = v;
        }
    }
}

// ---------------- generic fp16 GEMM (modes 1,2; 1 or 2 A terms) -------------
template<int BM, int BN, int WM, int WN, int MODE, int TERMS>
__global__ void __launch_bounds__((BM / WM) * (BN / WN) * 32)
mma_gemm(const __half* __restrict__ Ah, const __half* __restrict__ Al, int lda,
         const __half* __restrict__ Bm, int ldb, int K,
         float* __restrict__ C, int ldc,
         const float* __restrict__ bias,
         const float* __restrict__ srow, const float* __restrict__ ucol,
         __half* __restrict__ Ch)
{
    constexpr int NT = (BM / WM) * (BN / WN) * 32;
    constexpr int MF = WM / 16;
    constexpr int NF = WN / 8;
    constexpr int STAGE = (TERMS * BM + BN) * 64;
    constexpr int CHA = BM * 4;
    constexpr int CHB = BN * 4;
    constexpr int CHT = TERMS * CHA + CHB;

    extern __shared__ char smem[];
    const uint32_t sbase = smem_u32(smem);
    const int tid  = threadIdx.x;
    const int lane = tid & 31;
    const int warp = tid >> 5;
    const int wm0 = (warp / (BN / WN)) * WM;
    const int wn0 = (warp % (BN / WN)) * WN;
    const int m0 = blockIdx.y * BM;
    const int n0 = blockIdx.x * BN;

    float acc[MF][NF][4];
    #pragma unroll
    for (int i = 0; i < MF; i++)
        #pragma unroll
        for (int j = 0; j < NF; j++)
            #pragma unroll
            for (int q = 0; q < 4; q++) acc[i][j][q] = 0.f;

    auto load_stage = [&](int kt, int s) {
        const int k0 = kt * 32;
        const uint32_t tb = sbase + s * STAGE;
        #pragma unroll
        for (int q = 0; q < CHT / NT; q++) {
            const int i = tid + q * NT;
            const __half* src;
            int toff, rr;
            if (i < CHA) {
                rr = i >> 2; src = Ah + (size_t)(m0 + rr) * lda; toff = 0;
            } else if (TERMS == 2 && i < 2 * CHA) {
                int j = i - CHA; rr = j >> 2;
                src = Al + (size_t)(m0 + rr) * lda; toff = BM * 64;
            } else {
                int j = i - TERMS * CHA; rr = j >> 2;
                src = Bm + (size_t)(n0 + rr) * ldb; toff = TERMS * BM * 64;
            }
            const int c = i & 3;
            uint32_t dst = tb + toff + rr * 64 + ((c * 16) ^ (((rr >> 1) & 3) << 4));
            cp_async16(dst, src + k0 + c * 8);
        }
    };

    const int KT = K >> 5;
    load_stage(0, 0); cp_commit();
    load_stage(1, 1); cp_commit();

    const int li  = lane & 15;
    const int khb = (lane >> 4) << 4;
    const int swz = ((li >> 1) & 3) << 4;

    for (int kt = 0; kt < KT; kt++) {
        const int s = kt % 3;
        if (kt + 2 < KT) load_stage(kt + 2, (kt + 2) % 3);
        cp_commit();
        cp_wait2();
        __syncthreads();

        const uint32_t tA  = sbase + s * STAGE;
        const uint32_t tAl = tA + BM * 64;
        const uint32_t tB  = tA + TERMS * BM * 64;

        #pragma unroll
        for (int kk = 0; kk < 2; kk++) {
            const int cb = kk * 32;
            const uint32_t coff = (uint32_t)((cb + khb) ^ swz);
            uint32_t ah[MF][4], al_[MF][4];
            #pragma unroll
            for (int mf = 0; mf < MF; mf++) {
                uint32_t ro = (wm0 + mf * 16 + li) * 64 + coff;
                ldsm4(ah[mf], tA + ro);
                if (TERMS == 2) ldsm4(al_[mf], tAl + ro);
            }
            uint32_t bh[NF][2];
            #pragma unroll
            for (int nf2 = 0; nf2 < NF / 2; nf2++) {
                uint32_t ro = (wn0 + nf2 * 16 + li) * 64 + coff;
                uint32_t t[4];
                ldsm4(t, tB + ro);
                bh[2 * nf2][0] = t[0]; bh[2 * nf2][1] = t[2];
                bh[2 * nf2 + 1][0] = t[1]; bh[2 * nf2 + 1][1] = t[3];
            }
            #pragma unroll
            for (int mf = 0; mf < MF; mf++)
                #pragma unroll
                for (int nf = 0; nf < NF; nf++) {
                    mma16816(acc[mf][nf], ah[mf], bh[nf]);
                    if (TERMS == 2) mma16816(acc[mf][nf], al_[mf], bh[nf]);
                }
        }
        __syncthreads();
    }

    float* st = reinterpret_cast<float*>(smem) + warp * (WM * 33);
    #pragma unroll
    for (int mf = 0; mf < MF; mf++)
        #pragma unroll
        for (int nf = 0; nf < NF; nf++)
            #pragma unroll
            for (int i = 0; i < 2; i++) {
                int r = mf * 16 + (lane >> 2) + 8 * i;
                int c = nf * 8 + 2 * (lane & 3);
                st[r * 33 + c]     = acc[mf][nf][2 * i];
                st[r * 33 + c + 1] = acc[mf][nf][2 * i + 1];
            }
    __syncwarp();
    #pragma unroll
    for (int rr = lane; rr < WM; rr += 32) {
        const int m = m0 + wm0 + rr;
        const int nbase = n0 + wn0;
        if (MODE == 1) {
            const float tm = srow[m];
            #pragma unroll
            for (int c = 0; c < WN; c += 2) {
                int n = nbase + c;
                float v0 = st[rr * 33 + c]     + tm * ucol[n]     + bias[n];
                float v1 = st[rr * 33 + c + 1] + tm * ucol[n + 1] + bias[n + 1];
                __half2 ph;
                ph.x = __float2half_rn(v0); ph.y = __float2half_rn(v1);
                *reinterpret_cast<__half2*>(Ch + (size_t)m * ldc + n) = ph;
            }
        } else {
            #pragma unroll
            for (int c4 = 0; c4 < WN; c4 += 4) {
                float4 v;
                v.x = st[rr * 33 + c4];
                v.y = st[rr * 33 + c4 + 1];
                v.z = st[rr * 33 + c4 + 2];
                v.w = st[rr * 33 + c4 + 3];
                int n = nbase + c4;
                v.x += bias[n]; v.y += bias[n + 1];
                v.z += bias[n + 2]; v.w += bias[n + 3];
                *reinterpret_cast<float4*>(C + (size_t)m * ldc + nbase + c4) = v;
            }
        }
    }
}

// ---------------- persistent fused LSTM, BK=64, atomic barrier (R12) ---------
__global__ void __launch_bounds__(128)
lstm_persist(const __half* __restrict__ hhb, const __half* __restrict__ hlb,
             const __half* __restrict__ Bm,
             const float* __restrict__ xg, float* __restrict__ cstate,
             float* __restrict__ houtf,
             __half* __restrict__ hhw, __half* __restrict__ hlw)
{
    constexpr int BM = 32, BN = 64, NT = 128, NF = 4;
    constexpr int STAGE = (2 * BM + BN) * 128;   // 16384
    constexpr int CHA = BM * 8, CHB = BN * 8, CHT = 2 * CHA + CHB;

    extern __shared__ char smem[];
    const uint32_t sbase = smem_u32(smem);
    const int tid  = threadIdx.x;
    const int lane = tid & 31;
    const int warp = tid >> 5;
    const int wm0 = (warp >> 1) * 16;
    const int wn0 = (warp & 1) * 32;
    const int m0 = blockIdx.y * BM;
    const int n0 = blockIdx.x * BN;
    const int li  = lane & 15;
    const int qhb = lane >> 4;

    auto dev_barrier = [&](unsigned sv) {
        __threadfence();
        __syncthreads();
        if (tid == 0) {
            atomicAdd(&g_bar, 1u);
            volatile unsigned* vb = &g_bar;
            const unsigned target = 256u * sv;
            while (*vb < target) { }
        }
        __syncthreads();
    };

    // ---- step 0: h=c=0, gates = xg row ----
    {
        __half* Oh = hhw;
        __half* Ol = hlw;
        const float* xgl = xg;
        #pragma unroll
        for (int qsel = 0; qsel < NF / 2; qsel++) {
            const int nb = n0 + wn0 + qsel * 16;
            const int a  = lane & 3;
            const int j  = 4 * (nb >> 4) + a;
            #pragma unroll
            for (int i = 0; i < 2; i++) {
                const int m = m0 + wm0 + (lane >> 2) + 8 * i;
                const float* xrow = xgl + (size_t)m * (L_SZ * G4);
                float2 xif = *reinterpret_cast<const float2*>(xrow + nb + 2 * a);
                float2 xgo = *reinterpret_cast<const float2*>(xrow + nb + 8 + 2 * a);
                float ig = sigf(xif.x);
                float gg = tanhf(xgo.x), og = sigf(xgo.y);
                const int gi = (m << 10) + j;
                float cv = ig * gg;
                cstate[gi] = cv;
                float hv = og * tanhf(cv);
                __half hi, lo; split_h(hv, hi, lo);
                Oh[gi] = hi; Ol[gi] = lo;
            }
        }
        dev_barrier(1u);
    }

    for (int l = 1; l < L_SZ; l++) {
        const __half* Ah = hhb + (size_t)((l + 1) & 1) * (B_SZ * H_SZ);
        const __half* Al = hlb + (size_t)((l + 1) & 1) * (B_SZ * H_SZ);
        __half* Oh = hhw + (size_t)(l & 1) * (B_SZ * H_SZ);
        __half* Ol = hlw + (size_t)(l & 1) * (B_SZ * H_SZ);
        const float* xgl = xg + (size_t)l * G4;

        float acc[NF][4];
        #pragma unroll
        for (int j = 0; j < NF; j++)
            #pragma unroll
            for (int q = 0; q < 4; q++) acc[j][q] = 0.f;

        auto load_stage = [&](int kt, int s) {
            const int k0 = kt * 64;
            const uint32_t tb = sbase + s * STAGE;
            #pragma unroll
            for (int q = 0; q < CHT / NT; q++) {
                const int i = tid + q * NT;
                const __half* src;
                int toff, rr;
                if (i < CHA) {
                    rr = i >> 3; src = Ah + (size_t)(m0 + rr) * H_SZ; toff = 0;
                } else if (i < 2 * CHA) {
                    int j = i - CHA; rr = j >> 3;
                    src = Al + (size_t)(m0 + rr) * H_SZ; toff = BM * 128;
                } else {
                    int j = i - 2 * CHA; rr = j >> 3;
                    src = Bm + (size_t)(n0 + rr) * H_SZ; toff = 2 * BM * 128;
                }
                const int c = i & 7;
                uint32_t dst = tb + toff + rr * 128 + ((c ^ (rr & 7)) << 4);
                cp_async16(dst, src + k0 + c * 8);
            }
        };

        const int KT = H_SZ >> 6;   // 16
        load_stage(0, 0); cp_commit();
        load_stage(1, 1); cp_commit();

        for (int kt = 0; kt < KT; kt++) {
            const int s = kt % 3;
            if (kt + 2 < KT) load_stage(kt + 2, (kt + 2) % 3);
            cp_commit();
            cp_wait2();
            __syncthreads();

            const uint32_t tA  = sbase + s * STAGE;
            const uint32_t tAl = tA + BM * 128;
            const uint32_t tB  = tA + 2 * BM * 128;

            #pragma unroll
            for (int kk = 0; kk < 4; kk++) {
                const int q = kk * 2 + qhb;
                const uint32_t sw = (uint32_t)((q ^ (li & 7)) << 4);
                uint32_t ah[4], al_[4];
                {
                    uint32_t ro = (wm0 + li) * 128 + sw;
                    ldsm4(ah,  tA  + ro);
                    ldsm4(al_, tAl + ro);
                }
                uint32_t bh[NF][2];
                #pragma unroll
                for (int nf2 = 0; nf2 < NF / 2; nf2++) {
                    uint32_t ro = (wn0 + nf2 * 16 + li) * 128 + sw;
                    uint32_t t[4];
                    ldsm4(t, tB + ro);
                    bh[2 * nf2][0] = t[0]; bh[2 * nf2][1] = t[2];
                    bh[2 * nf2 + 1][0] = t[1]; bh[2 * nf2 + 1][1] = t[3];
                }
                #pragma unroll
                for (int nf = 0; nf < NF; nf++) {
                    mma16816(acc[nf], ah,  bh[nf]);
                    mma16816(acc[nf], al_, bh[nf]);
                }
            }
            __syncthreads();
        }

        // fused gate nonlinearity + state update
        #pragma unroll
        for (int qsel = 0; qsel < NF / 2; qsel++) {
            const int nb = n0 + wn0 + qsel * 16;
            const int a  = lane & 3;
            const int j  = 4 * (nb >> 4) + a;
            #pragma unroll
            for (int i = 0; i < 2; i++) {
                const int m = m0 + wm0 + (lane >> 2) + 8 * i;
                const float* xrow = xgl + (size_t)m * (L_SZ * G4);
                float2 xif = *reinterpret_cast<const float2*>(xrow + nb + 2 * a);
                float2 xgo = *reinterpret_cast<const float2*>(xrow + nb + 8 + 2 * a);
                float xi = acc[2 * qsel][2 * i]         + xif.x;
                float xf = acc[2 * qsel][2 * i + 1]     + xif.y;
                float xgv = acc[2 * qsel + 1][2 * i]    + xgo.x;
                float xo = acc[2 * qsel + 1][2 * i + 1] + xgo.y;
                float ig = sigf(xi), fg = sigf(xf);
                float gg = tanhf(xgv), og = sigf(xo);
                const int gi = (m << 10) + j;
                float cv = fg * cstate[gi] + ig * gg;
                cstate[gi] = cv;
                float hv = og * tanhf(cv);
                houtf[gi] = hv;
                __half hi, lo; split_h(hv, hi, lo);
                Oh[gi] = hi; Ol[gi] = lo;
            }
        }

        dev_barrier((unsigned)(l + 1));
    }
}

// ---------------- converts (8 floats/thread, 16B stores) ---------------------
__global__ void conv_round(const float* __restrict__ src, int C, int srcld,
                           __half* __restrict__ dst)
{
    int c8 = (blockIdx.x * blockDim.x + threadIdx.x) * 8;
    int r = blockIdx.y;
    if (c8 >= C) return;
    float4 x0 = *reinterpret_cast<const float4*>(src + (size_t)r * srcld + c8);
    float4 x1 = *reinterpret_cast<const float4*>(src + (size_t)r * srcld + c8 + 4);
    uint4 p;
    p.x = pack2(x0.x, x0.y); p.y = pack2(x0.z, x0.w);
    p.z = pack2(x1.x, x1.y); p.w = pack2(x1.z, x1.w);
    *reinterpret_cast<uint4*>(dst + (size_t)r * C + c8) = p;
}

__global__ void conv_perm_round(const float* __restrict__ src, int cols,
                                __half* __restrict__ dst)
{
    int c8 = (blockIdx.x * blockDim.x + threadIdx.x) * 8;
    int r = blockIdx.y;
    if (c8 >= cols) return;
    int gate = ((r >> 3) & 1) * 2 + (r & 1);
    int cell = 4 * (r >> 4) + ((r >> 1) & 3);
    int orig = gate * 1024 + cell;
    float4 x0 = *reinterpret_cast<const float4*>(src + (size_t)orig * cols + c8);
    float4 x1 = *reinterpret_cast<const float4*>(src + (size_t)orig * cols + c8 + 4);
    uint4 p;
    p.x = pack2(x0.x, x0.y); p.y = pack2(x0.z, x0.w);
    p.z = pack2(x1.x, x1.y); p.w = pack2(x1.z, x1.w);
    *reinterpret_cast<uint4*>(dst + (size_t)r * cols + c8) = p;
}

__global__ void prep_kernel(const float* __restrict__ Wvt,
                            const float* __restrict__ wtw,
                            const float* __restrict__ wtb,
                            const float* __restrict__ bih,
                            const float* __restrict__ bhh)
{
    int i = blockIdx.x * blockDim.x + threadIdx.x;
    if (i == 0) g_bar = 0;
    if (i < HIN) {
        const float* row = Wvt + (size_t)i * (HIN + 128) + HIN;
        float u = 0.f, ub = 0.f;
        #pragma unroll 4
        for (int j = 0; j < 128; j++) { float w = row[j]; u += w * wtw[j]; ub += w * wtb[j]; }
        g_u[i] = u; g_ub[i] = ub;
    } else if (i < HIN + G4) {
        int r = i - HIN;
        int gate = ((r >> 3) & 1) * 2 + (r & 1);
        int cell = 4 * (r >> 4) + ((r >> 1) & 3);
        g_biasp[r] = bih[gate * 1024 + cell] + bhh[gate * 1024 + cell];
    } else if (i < HIN + G4 + HIN * HIN / 8) {
        int w = i - (HIN + G4);
        int r = w >> 6;
        int c8 = (w & 63) * 8;
        float4 x0 = *reinterpret_cast<const float4*>(Wvt + (size_t)r * (HIN + 128) + c8);
        float4 x1 = *reinterpret_cast<const float4*>(Wvt + (size_t)r * (HIN + 128) + c8 + 4);
        uint4 p;
        p.x = pack2(x0.x, x0.y); p.y = pack2(x0.z, x0.w);
        p.z = pack2(x1.x, x1.y); p.w = pack2(x1.z, x1.w);
        *reinterpret_cast<uint4*>(g_wvt + (size_t)r * HIN + c8) = p;
    }
}

__global__ void reduce_conv(void)
{
    int idx = blockIdx.x * 256 + threadIdx.x;
    float s = 0.f;
    #pragma unroll
    for (int z = 0; z < KSPLIT; z++) s += g_split[(size_t)z * ML * HIN + idx];
    __half hi, lo; split_h(s, hi, lo);
    g_vdh[idx] = hi; g_vdl[idx] = lo;
}

__global__ void pred_kernel(const float* __restrict__ lw,
                            const float* __restrict__ lb,
                            float* __restrict__ out)
{
    int b = blockIdx.x, tid = threadIdx.x;
    const float* hr = g_h + (size_t)b * H_SZ;
    float s = 0.f;
    for (int k = tid; k < H_SZ; k += 128) s += hr[k] * lw[k];
    __shared__ float red[128];
    red[tid] = s; __syncthreads();
    for (int off = 64; off > 0; off >>= 1) {
        if (tid < off) red[tid] += red[tid + off];
        __syncthreads();
    }
    if (tid == 0) out[b] = red[0] + lb[0];
}

// ---------------- launch -----------------------------------------------------
#define SMEM_G1   67584                          // max(pipeline 40960, epilogue)
#define SMEM_G2   ((2 * 64 + 128) * 64 * 3)      // 49152 (BM=64 2-term)
#define SMEM_T1   67584
#define SMEM_LSTM ((2 * 32 + 64) * 128 * 3)      // 49152

extern "C" void kernel_launch(void* const* d_in, const int* in_sizes, int n_in,
                              void* d_out, int out_size)
{
    const float* v   = (const float*)d_in[0];
    const float* t   = (const float*)d_in[1];
    const float* Wd  = (const float*)d_in[2];
    const float* wtw = (const float*)d_in[3];
    const float* wtb = (const float*)d_in[4];
    const float* Wvt = (const float*)d_in[5];
    const float* Wih = (const float*)d_in[6];
    const float* Whh = (const float*)d_in[7];
    const float* bih = (const float*)d_in[8];
    const float* bhh = (const float*)d_in[9];
    const float* lw  = (const float*)d_in[10];
    const float* lb  = (const float*)d_in[11];
    float* out = (float*)d_out;

    __half *p_wd, *p_vdh, *p_vdl, *p_wvt, *p_ih, *p_wih, *p_whh, *p_hh, *p_hl;
    float *p_split, *p_xg, *p_h, *p_c, *p_u, *p_ub, *p_biasp;
    cudaGetSymbolAddress((void**)&p_wd, g_wd);
    cudaGetSymbolAddress((void**)&p_vdh, g_vdh); cudaGetSymbolAddress((void**)&p_vdl, g_vdl);
    cudaGetSymbolAddress((void**)&p_wvt, g_wvt);
    cudaGetSymbolAddress((void**)&p_ih, g_ih);
    cudaGetSymbolAddress((void**)&p_wih, g_wih); cudaGetSymbolAddress((void**)&p_whh, g_whh);
    cudaGetSymbolAddress((void**)&p_hh, g_hh);   cudaGetSymbolAddress((void**)&p_hl, g_hl);
    cudaGetSymbolAddress((void**)&p_split, g_split);
    cudaGetSymbolAddress((void**)&p_xg, g_xg);
    cudaGetSymbolAddress((void**)&p_h, g_h);     cudaGetSymbolAddress((void**)&p_c, g_c);
    cudaGetSymbolAddress((void**)&p_u, g_u);     cudaGetSymbolAddress((void**)&p_ub, g_ub);
    cudaGetSymbolAddress((void**)&p_biasp, g_biasp);

    cudaFuncSetAttribute(gemm1_fused, cudaFuncAttributeMaxDynamicSharedMemorySize, SMEM_G1);
    cudaFuncSetAttribute(mma_gemm<64, 128, 32, 32, 1, 2>, cudaFuncAttributeMaxDynamicSharedMemorySize, SMEM_G2);
    cudaFuncSetAttribute(mma_gemm<128, 128, 64, 32, 2, 1>, cudaFuncAttributeMaxDynamicSharedMemorySize, SMEM_T1);
    cudaFuncSetAttribute(lstm_persist, cudaFuncAttributeMaxDynamicSharedMemorySize, SMEM_LSTM);

    // 1) prep  2) W_down round  3) W_ih perm-round
    prep_kernel<<<(HIN + G4 + HIN * HIN / 8 + 255) / 256, 256>>>(Wvt, wtw, wtb, bih, bhh);
    conv_round<<<dim3((N_SZ / 8 + 255) / 256, HIN), 256>>>(Wd, N_SZ, N_SZ, p_wd);
    conv_perm_round<<<dim3(1, G4), 256>>>(Wih, HIN, p_wih);

    // 4) GEMM1 (LDG-reg convert, 1-term, split-K=4)
    gemm1_fused<<<dim3(HIN / 128, ML / 128, KSPLIT), 256, SMEM_G1>>>(
        v, N_SZ, p_wd, N_SZ, p_split, HIN, (size_t)ML * HIN);

    // 5) reduce partials -> vd fp16 split
    reduce_conv<<<(ML * HIN) / 256, 256>>>();

    // 6) GEMM2 (2-term, 64x128 tiles -> 128 CTAs)
    mma_gemm<64, 128, 32, 32, 1, 2><<<dim3(HIN / 128, ML / 64), 256, SMEM_G2>>>(
        p_vdh, p_vdl, HIN, p_wvt, HIN, HIN,
        nullptr, HIN, p_ub, t, p_u, p_ih);

    // 7) GEMM3 (1-term): xg = inputs_fp16 @ Wih_perm^T + bias_perm
    mma_gemm<128, 128, 64, 32, 2, 1><<<dim3(G4 / 128, ML / 128), 256, SMEM_T1>>>(
        p_ih, nullptr, HIN, p_wih, HIN, HIN,
        p_xg, G4, p_biasp, nullptr, nullptr, nullptr);

    // 8) W_hh perm-round  9) persistent LSTM steps 0..15 (atomic barrier)
    conv_perm_round<<<dim3(1, G4), 256>>>(Whh, H_SZ, p_whh);
    lstm_persist<<<dim3(G4 / 64, B_SZ / 32), 128, SMEM_LSTM>>>(
        p_hh, p_hl, p_whh, p_xg, p_c, p_h, p_hh, p_hl);

    // 10) pred
    pred_kernel<<<B_SZ, 128>>>(lw, lb, out);
}

// round 15
// speedup vs baseline: 1.4569x; 1.1358x over previous
#include <cuda_runtime.h>
#include <cuda_fp16.h>
#include <cstdint>
#include <math.h>

// ---------------- dims ------------------------------------------------------
#define B_SZ 128
#define L_SZ 16
#define N_SZ 20000
#define HIN  512
#define H_SZ 1024
#define G4   4096
#define ML   2048
#define KSPLIT 4
// split-K chunks: 5024,5024,5024,4928 (all %32==0, sum 20000)

// ---------------- device global scratch ------------------------------------
__device__ __half g_wd[(size_t)HIN * N_SZ];       // W_down rounded fp16
__device__ float g_split[KSPLIT * ML * HIN];
__device__ __half g_vdh[ML * HIN];                // vd rounded fp16
__device__ __half g_wvt[HIN * HIN];               // W_vt[:, :512] rounded
__device__ __half g_ih[ML * HIN];                 // inputs rounded fp16
__device__ __half g_wih[G4 * HIN];                // W_ih permuted rounded
__device__ __half g_whh[(size_t)G4 * H_SZ];       // W_hh permuted rounded
__device__ float g_xg[(size_t)ML * G4];           // permuted gate cols
__device__ __half g_hh[2 * B_SZ * H_SZ];          // h rounded, double buffered
__device__ float g_h[B_SZ * H_SZ];
__device__ float g_c[B_SZ * H_SZ];
__device__ float g_u[HIN];
__device__ float g_ub[HIN];
__device__ float g_biasp[G4];
__device__ unsigned g_bar;                        // LSTM barrier counter

// ---------------- helpers ---------------------------------------------------
__device__ __forceinline__ uint32_t smem_u32(const void* p) {
    uint32_t a;
    asm("{ .reg .u64 t; cvta.to.shared.u64 t, %1; cvt.u32.u64 %0, t; }" : "=r"(a) : "l"(p));
    return a;
}
__device__ __forceinline__ void cp_async16(uint32_t dst, const void* src) {
    asm volatile("cp.async.cg.shared.global [%0], [%1], 16;" :: "r"(dst), "l"(src));
}
__device__ __forceinline__ void cp_commit() {
    asm volatile("cp.async.commit_group;" ::: "memory");
}
__device__ __forceinline__ void cp_wait1() {
    asm volatile("cp.async.wait_group 1;" ::: "memory");
}
__device__ __forceinline__ void cp_wait2() {
    asm volatile("cp.async.wait_group 2;" ::: "memory");
}
__device__ __forceinline__ void ldsm4(uint32_t* r, uint32_t addr) {
    asm volatile("ldmatrix.sync.aligned.m8n8.x4.shared.b16 {%0,%1,%2,%3}, [%4];"
        : "=r"(r[0]), "=r"(r[1]), "=r"(r[2]), "=r"(r[3]) : "r"(addr));
}
__device__ __forceinline__ void mma16816(float* c, const uint32_t* a, const uint32_t* b) {
    asm volatile("mma.sync.aligned.m16n8k16.row.col.f32.f16.f16.f32 "
        "{%0,%1,%2,%3}, {%4,%5,%6,%7}, {%8,%9}, {%0,%1,%2,%3};"
        : "+f"(c[0]), "+f"(c[1]), "+f"(c[2]), "+f"(c[3])
        : "r"(a[0]), "r"(a[1]), "r"(a[2]), "r"(a[3]), "r"(b[0]), "r"(b[1]));
}
__device__ __forceinline__ float sigf(float x) { return 1.f / (1.f + expf(-x)); }
__device__ __forceinline__ uint32_t pack2(float a, float b) {
    __half2 t; t.x = __float2half_rn(a); t.y = __float2half_rn(b);
    return *reinterpret_cast<uint32_t*>(&t);
}

// fp16 smem tile (64B rows):  16B chunk c of row r at r*64 + ((c*16) ^ (((r>>1)&3)<<4))
// fp16 smem tile (128B rows): 16B chunk c of row r at r*128 + ((c ^ (r&7))<<4)

// ---------------- GEMM1: LDG->reg fp32, convert->fp16 STS, 1-term HMMA ------
__global__ void __launch_bounds__(256, 2)
gemm1_fused(const float* __restrict__ Afp, int lda,
            const __half* __restrict__ Bm, int ldb,
            float* __restrict__ C, int ldc, size_t zstride)
{
    constexpr int BM = 128, BN = 128, WM = 64, WN = 32, MF = 4, NF = 4;
    constexpr int B16S = 128 * 64;                 // 8192 per B stage
    constexpr int OFF_AH = 3 * B16S;               // 24576; Ah[2] -> 40960 pipeline

    extern __shared__ char smem[];
    const uint32_t sbase = smem_u32(smem);
    const int tid  = threadIdx.x;
    const int lane = tid & 31;
    const int warp = tid >> 5;
    const int wm0 = (warp / (BN / WN)) * WM;
    const int wn0 = (warp % (BN / WN)) * WN;
    const int m0 = blockIdx.y * BM;
    const int n0 = blockIdx.x * BN;
    const int kbase = blockIdx.z * 5024;
    const int Kz = (blockIdx.z == 3) ? 4928 : 5024;
    C += (size_t)blockIdx.z * zstride;

    float acc[MF][NF][4];
    #pragma unroll
    for (int i = 0; i < MF; i++)
        #pragma unroll
        for (int j = 0; j < NF; j++)
            #pragma unroll
            for (int q = 0; q < 4; q++) acc[i][j][q] = 0.f;

    auto loadB = [&](int kt) {
        const int k0 = kbase + kt * 32;
        const uint32_t tb = sbase + (kt % 3) * B16S;
        #pragma unroll
        for (int q = 0; q < 2; q++) {
            const int i = tid + q * 256;
            int row = i >> 2, c = i & 3;
            uint32_t dst = tb + row * 64 + ((c * 16) ^ (((row >> 1) & 3) << 4));
            cp_async16(dst, Bm + (size_t)(n0 + row) * ldb + k0 + c * 8);
        }
    };

    float4 pa[4];
    auto ldga = [&](int kt) {
        const int k0 = kbase + kt * 32;
        #pragma unroll
        for (int q = 0; q < 4; q++) {
            const int i = tid + q * 256;
            int row = i >> 3, c = i & 7;
            pa[q] = *reinterpret_cast<const float4*>(
                Afp + (size_t)(m0 + row) * lda + k0 + c * 4);
        }
    };
    auto convert = [&](int kt) {
        char* ahb = smem + OFF_AH + (kt & 1) * 8192;
        #pragma unroll
        for (int q = 0; q < 4; q++) {
            const int i = tid + q * 256;
            int row = i >> 3, c = i & 7;
            uint2 p;
            p.x = pack2(pa[q].x, pa[q].y);
            p.y = pack2(pa[q].z, pa[q].w);
            uint32_t so = row * 64 + (((c >> 1) * 16) ^ (((row >> 1) & 3) << 4)) + (c & 1) * 8;
            *reinterpret_cast<uint2*>(ahb + so) = p;
        }
    };

    const int KT = Kz >> 5;
    loadB(0); cp_commit();
    loadB(1); cp_commit();
    ldga(0);
    convert(0);
    ldga(1);

    const int li  = lane & 15;
    const int khb = (lane >> 4) << 4;
    const int swz = ((li >> 1) & 3) << 4;

    for (int kt = 0; kt < KT; kt++) {
        if (kt + 2 < KT) loadB(kt + 2);
        cp_commit();
        cp_wait1();
        __syncthreads();

        if (kt + 1 < KT) {
            convert(kt + 1);
            if (kt + 2 < KT) ldga(kt + 2);
        }

        {
            const uint32_t tAh = sbase + OFF_AH + (kt & 1) * 8192;
            const uint32_t tB  = sbase + (kt % 3) * B16S;
            #pragma unroll
            for (int kk = 0; kk < 2; kk++) {
                const int cb = kk * 32;
                const uint32_t coff = (uint32_t)((cb + khb) ^ swz);
                uint32_t ah[MF][4];
                #pragma unroll
                for (int mf = 0; mf < MF; mf++) {
                    uint32_t ro = (wm0 + mf * 16 + li) * 64 + coff;
                    ldsm4(ah[mf], tAh + ro);
                }
                uint32_t bh[NF][2];
                #pragma unroll
                for (int nf2 = 0; nf2 < NF / 2; nf2++) {
                    uint32_t ro = (wn0 + nf2 * 16 + li) * 64 + coff;
                    uint32_t t[4];
                    ldsm4(t, tB + ro);
                    bh[2 * nf2][0] = t[0]; bh[2 * nf2][1] = t[2];
                    bh[2 * nf2 + 1][0] = t[1]; bh[2 * nf2 + 1][1] = t[3];
                }
                #pragma unroll
                for (int mf = 0; mf < MF; mf++)
                    #pragma unroll
                    for (int nf = 0; nf < NF; nf++)
                        mma16816(acc[mf][nf], ah[mf], bh[nf]);
            }
        }
        __syncthreads();
    }

    float* st = reinterpret_cast<float*>(smem) + warp * (WM * 33);
    #pragma unroll
    for (int mf = 0; mf < MF; mf++)
        #pragma unroll
        for (int nf = 0; nf < NF; nf++)
            #pragma unroll
            for (int i = 0; i < 2; i++) {
                int r = mf * 16 + (lane >> 2) + 8 * i;
                int c = nf * 8 + 2 * (lane & 3);
                st[r * 33 + c]     = acc[mf][nf][2 * i];
                st[r * 33 + c + 1] = acc[mf][nf][2 * i + 1];
            }
    __syncwarp();
    #pragma unroll
    for (int rr = lane; rr < WM; rr += 32) {
        const int m = m0 + wm0 + rr;
        #pragma unroll
        for (int c4 = 0; c4 < WN; c4 += 4) {
            float4 v;
            v.x = st[rr * 33 + c4];     v.y = st[rr * 33 + c4 + 1];
            v.z = st[rr * 33 + c4 + 2]; v.w = st[rr * 33 + c4 + 3];
            *reinterpret_cast<float4*>(C + (size_t)m * ldc + n0 + wn0 + c4) = v;
        }
    }
}

// ---------------- generic fp16 GEMM (modes 1,2; 1-term A) --------------------
// MODE 1: += srow[m]*ucol[n] + bias[n]; fp16 out to Ch
// MODE 2: += bias[n]; fp32 out
template<int BM, int BN, int WM, int WN, int MODE>
__global__ void __launch_bounds__((BM / WM) * (BN / WN) * 32)
mma_gemm(const __half* __restrict__ Ah, int lda,
         const __half* __restrict__ Bm, int ldb, int K,
         float* __restrict__ C, int ldc,
         const float* __restrict__ bias,
         const float* __restrict__ srow, const float* __restrict__ ucol,
         __half* __restrict__ Ch)
{
    constexpr int NT = (BM / WM) * (BN / WN) * 32;
    constexpr int MF = WM / 16;
    constexpr int NF = WN / 8;
    constexpr int STAGE = (BM + BN) * 64;
    constexpr int CHA = BM * 4;
    constexpr int CHB = BN * 4;
    constexpr int CHT = CHA + CHB;

    extern __shared__ char smem[];
    const uint32_t sbase = smem_u32(smem);
    const int tid  = threadIdx.x;
    const int lane = tid & 31;
    const int warp = tid >> 5;
    const int wm0 = (warp / (BN / WN)) * WM;
    const int wn0 = (warp % (BN / WN)) * WN;
    const int m0 = blockIdx.y * BM;
    const int n0 = blockIdx.x * BN;

    float acc[MF][NF][4];
    #pragma unroll
    for (int i = 0; i < MF; i++)
        #pragma unroll
        for (int j = 0; j < NF; j++)
            #pragma unroll
            for (int q = 0; q < 4; q++) acc[i][j][q] = 0.f;

    auto load_stage = [&](int kt, int s) {
        const int k0 = kt * 32;
        const uint32_t tb = sbase + s * STAGE;
        #pragma unroll
        for (int q = 0; q < CHT / NT; q++) {
            const int i = tid + q * NT;
            const __half* src;
            int toff, rr;
            if (i < CHA) {
                rr = i >> 2; src = Ah + (size_t)(m0 + rr) * lda; toff = 0;
            } else {
                int j = i - CHA; rr = j >> 2;
                src = Bm + (size_t)(n0 + rr) * ldb; toff = BM * 64;
            }
            const int c = i & 3;
            uint32_t dst = tb + toff + rr * 64 + ((c * 16) ^ (((rr >> 1) & 3) << 4));
            cp_async16(dst, src + k0 + c * 8);
        }
    };

    const int KT = K >> 5;
    load_stage(0, 0); cp_commit();
    load_stage(1, 1); cp_commit();

    const int li  = lane & 15;
    const int khb = (lane >> 4) << 4;
    const int swz = ((li >> 1) & 3) << 4;

    for (int kt = 0; kt < KT; kt++) {
        const int s = kt % 3;
        if (kt + 2 < KT) load_stage(kt + 2, (kt + 2) % 3);
        cp_commit();
        cp_wait2();
        __syncthreads();

        const uint32_t tA = sbase + s * STAGE;
        const uint32_t tB = tA + BM * 64;

        #pragma unroll
        for (int kk = 0; kk < 2; kk++) {
            const int cb = kk * 32;
            const uint32_t coff = (uint32_t)((cb + khb) ^ swz);
            uint32_t ah[MF][4];
            #pragma unroll
            for (int mf = 0; mf < MF; mf++) {
                uint32_t ro = (wm0 + mf * 16 + li) * 64 + coff;
                ldsm4(ah[mf], tA + ro);
            }
            uint32_t bh[NF][2];
            #pragma unroll
            for (int nf2 = 0; nf2 < NF / 2; nf2++) {
                uint32_t ro = (wn0 + nf2 * 16 + li) * 64 + coff;
                uint32_t t[4];
                ldsm4(t, tB + ro);
                bh[2 * nf2][0] = t[0]; bh[2 * nf2][1] = t[2];
                bh[2 * nf2 + 1][0] = t[1]; bh[2 * nf2 + 1][1] = t[3];
            }
            #pragma unroll
            for (int mf = 0; mf < MF; mf++)
                #pragma unroll
                for (int nf = 0; nf < NF; nf++)
                    mma16816(acc[mf][nf], ah[mf], bh[nf]);
        }
        __syncthreads();
    }

    float* st = reinterpret_cast<float*>(smem) + warp * (WM * 33);
    #pragma unroll
    for (int mf = 0; mf < MF; mf++)
        #pragma unroll
        for (int nf = 0; nf < NF; nf++)
            #pragma unroll
            for (int i = 0; i < 2; i++) {
                int r = mf * 16 + (lane >> 2) + 8 * i;
                int c = nf * 8 + 2 * (lane & 3);
                st[r * 33 + c]     = acc[mf][nf][2 * i];
                st[r * 33 + c + 1] = acc[mf][nf][2 * i + 1];
            }
    __syncwarp();
    #pragma unroll
    for (int rr = lane; rr < WM; rr += 32) {
        const int m = m0 + wm0 + rr;
        const int nbase = n0 + wn0;
        if (MODE == 1) {
            const float tm = srow[m];
            #pragma unroll
            for (int c = 0; c < WN; c += 2) {
                int n = nbase + c;
                float v0 = st[rr * 33 + c]     + tm * ucol[n]     + bias[n];
                float v1 = st[rr * 33 + c + 1] + tm * ucol[n + 1] + bias[n + 1];
                __half2 ph;
                ph.x = __float2half_rn(v0); ph.y = __float2half_rn(v1);
                *reinterpret_cast<__half2*>(Ch + (size_t)m * ldc + n) = ph;
            }
        } else {
            #pragma unroll
            for (int c4 = 0; c4 < WN; c4 += 4) {
                float4 v;
                v.x = st[rr * 33 + c4];
                v.y = st[rr * 33 + c4 + 1];
                v.z = st[rr * 33 + c4 + 2];
                v.w = st[rr * 33 + c4 + 3];
                int n = nbase + c4;
                v.x += bias[n]; v.y += bias[n + 1];
                v.z += bias[n + 2]; v.w += bias[n + 3];
                *reinterpret_cast<float4*>(C + (size_t)m * ldc + nbase + c4) = v;
            }
        }
    }
}

// ---------------- persistent fused LSTM, BK=64, 1-term h, atomic barrier -----
__global__ void __launch_bounds__(128)
lstm_persist(const __half* __restrict__ hhb,
             const __half* __restrict__ Bm,
             const float* __restrict__ xg, float* __restrict__ cstate,
             float* __restrict__ houtf,
             __half* __restrict__ hhw)
{
    constexpr int BM = 32, BN = 64, NT = 128, NF = 4;
    constexpr int STAGE = (BM + BN) * 128;       // 12288
    constexpr int CHA = BM * 8, CHB = BN * 8, CHT = CHA + CHB;   // 768

    extern __shared__ char smem[];
    const uint32_t sbase = smem_u32(smem);
    const int tid  = threadIdx.x;
    const int lane = tid & 31;
    const int warp = tid >> 5;
    const int wm0 = (warp >> 1) * 16;
    const int wn0 = (warp & 1) * 32;
    const int m0 = blockIdx.y * BM;
    const int n0 = blockIdx.x * BN;
    const int li  = lane & 15;
    const int qhb = lane >> 4;

    auto dev_barrier = [&](unsigned sv) {
        __threadfence();
        __syncthreads();
        if (tid == 0) {
            atomicAdd(&g_bar, 1u);
            volatile unsigned* vb = &g_bar;
            const unsigned target = 256u * sv;
            while (*vb < target) { }
        }
        __syncthreads();
    };

    // ---- step 0: h=c=0, gates = xg row ----
    {
        __half* Oh = hhw;
        const float* xgl = xg;
        #pragma unroll
        for (int qsel = 0; qsel < NF / 2; qsel++) {
            const int nb = n0 + wn0 + qsel * 16;
            const int a  = lane & 3;
            const int j  = 4 * (nb >> 4) + a;
            #pragma unroll
            for (int i = 0; i < 2; i++) {
                const int m = m0 + wm0 + (lane >> 2) + 8 * i;
                const float* xrow = xgl + (size_t)m * (L_SZ * G4);
                float2 xif = *reinterpret_cast<const float2*>(xrow + nb + 2 * a);
                float2 xgo = *reinterpret_cast<const float2*>(xrow + nb + 8 + 2 * a);
                float ig = sigf(xif.x);
                float gg = tanhf(xgo.x), og = sigf(xgo.y);
                const int gi = (m << 10) + j;
                float cv = ig * gg;
                cstate[gi] = cv;
                float hv = og * tanhf(cv);
                Oh[gi] = __float2half_rn(hv);
            }
        }
        dev_barrier(1u);
    }

    for (int l = 1; l < L_SZ; l++) {
        const __half* Ah = hhb + (size_t)((l + 1) & 1) * (B_SZ * H_SZ);
        __half* Oh = hhw + (size_t)(l & 1) * (B_SZ * H_SZ);
        const float* xgl = xg + (size_t)l * G4;

        float acc[NF][4];
        #pragma unroll
        for (int j = 0; j < NF; j++)
            #pragma unroll
            for (int q = 0; q < 4; q++) acc[j][q] = 0.f;

        auto load_stage = [&](int kt, int s) {
            const int k0 = kt * 64;
            const uint32_t tb = sbase + s * STAGE;
            #pragma unroll
            for (int q = 0; q < CHT / NT; q++) {
                const int i = tid + q * NT;
                const __half* src;
                int toff, rr;
                if (i < CHA) {
                    rr = i >> 3; src = Ah + (size_t)(m0 + rr) * H_SZ; toff = 0;
                } else {
                    int j = i - CHA; rr = j >> 3;
                    src = Bm + (size_t)(n0 + rr) * H_SZ; toff = BM * 128;
                }
                const int c = i & 7;
                uint32_t dst = tb + toff + rr * 128 + ((c ^ (rr & 7)) << 4);
                cp_async16(dst, src + k0 + c * 8);
            }
        };

        const int KT = H_SZ >> 6;   // 16
        load_stage(0, 0); cp_commit();
        load_stage(1, 1); cp_commit();

        for (int kt = 0; kt < KT; kt++) {
            const int s = kt % 3;
            if (kt + 2 < KT) load_stage(kt + 2, (kt + 2) % 3);
            cp_commit();
            cp_wait2();
            __syncthreads();

            const uint32_t tA = sbase + s * STAGE;
            const uint32_t tB = tA + BM * 128;

            #pragma unroll
            for (int kk = 0; kk < 4; kk++) {
                const int q = kk * 2 + qhb;
                const uint32_t sw = (uint32_t)((q ^ (li & 7)) << 4);
                uint32_t ah[4];
                {
                    uint32_t ro = (wm0 + li) * 128 + sw;
                    ldsm4(ah, tA + ro);
                }
                uint32_t bh[NF][2];
                #pragma unroll
                for (int nf2 = 0; nf2 < NF / 2; nf2++) {
                    uint32_t ro = (wn0 + nf2 * 16 + li) * 128 + sw;
                    uint32_t t[4];
                    ldsm4(t, tB + ro);
                    bh[2 * nf2][0] = t[0]; bh[2 * nf2][1] = t[2];
                    bh[2 * nf2 + 1][0] = t[1]; bh[2 * nf2 + 1][1] = t[3];
                }
                #pragma unroll
                for (int nf = 0; nf < NF; nf++)
                    mma16816(acc[nf], ah, bh[nf]);
            }
            __syncthreads();
        }

        // fused gate nonlinearity + state update
        #pragma unroll
        for (int qsel = 0; qsel < NF / 2; qsel++) {
            const int nb = n0 + wn0 + qsel * 16;
            const int a  = lane & 3;
            const int j  = 4 * (nb >> 4) + a;
            #pragma unroll
            for (int i = 0; i < 2; i++) {
                const int m = m0 + wm0 + (lane >> 2) + 8 * i;
                const float* xrow = xgl + (size_t)m * (L_SZ * G4);
                float2 xif = *reinterpret_cast<const float2*>(xrow + nb + 2 * a);
                float2 xgo = *reinterpret_cast<const float2*>(xrow + nb + 8 + 2 * a);
                float xi = acc[2 * qsel][2 * i]         + xif.x;
                float xf = acc[2 * qsel][2 * i + 1]     + xif.y;
                float xgv = acc[2 * qsel + 1][2 * i]    + xgo.x;
                float xo = acc[2 * qsel + 1][2 * i + 1] + xgo.y;
                float ig = sigf(xi), fg = sigf(xf);
                float gg = tanhf(xgv), og = sigf(xo);
                const int gi = (m << 10) + j;
                float cv = fg * cstate[gi] + ig * gg;
                cstate[gi] = cv;
                float hv = og * tanhf(cv);
                houtf[gi] = hv;
                Oh[gi] = __float2half_rn(hv);
            }
        }

        dev_barrier((unsigned)(l + 1));
    }
}

// ---------------- converts (8 floats/thread, 16B stores) ---------------------
__global__ void conv_round(const float* __restrict__ src, int C, int srcld,
                           __half* __restrict__ dst)
{
    int c8 = (blockIdx.x * blockDim.x + threadIdx.x) * 8;
    int r = blockIdx.y;
    if (c8 >= C) return;
    float4 x0 = *reinterpret_cast<const float4*>(src + (size_t)r * srcld + c8);
    float4 x1 = *reinterpret_cast<const float4*>(src + (size_t)r * srcld + c8 + 4);
    uint4 p;
    p.x = pack2(x0.x, x0.y); p.y = pack2(x0.z, x0.w);
    p.z = pack2(x1.x, x1.y); p.w = pack2(x1.z, x1.w);
    *reinterpret_cast<uint4*>(dst + (size_t)r * C + c8) = p;
}

__global__ void conv_perm_round(const float* __restrict__ src, int cols,
                                __half* __restrict__ dst)
{
    int c8 = (blockIdx.x * blockDim.x + threadIdx.x) * 8;
    int r = blockIdx.y;
    if (c8 >= cols) return;
    int gate = ((r >> 3) & 1) * 2 + (r & 1);
    int cell = 4 * (r >> 4) + ((r >> 1) & 3);
    int orig = gate * 1024 + cell;
    float4 x0 = *reinterpret_cast<const float4*>(src + (size_t)orig * cols + c8);
    float4 x1 = *reinterpret_cast<const float4*>(src + (size_t)orig * cols + c8 + 4);
    uint4 p;
    p.x = pack2(x0.x, x0.y); p.y = pack2(x0.z, x0.w);
    p.z = pack2(x1.x, x1.y); p.w = pack2(x1.z, x1.w);
    *reinterpret_cast<uint4*>(dst + (size_t)r * cols + c8) = p;
}

__global__ void prep_kernel(const float* __restrict__ Wvt,
                            const float* __restrict__ wtw,
                            const float* __restrict__ wtb,
                            const float* __restrict__ bih,
                            const float* __restrict__ bhh)
{
    int i = blockIdx.x * blockDim.x + threadIdx.x;
    if (i == 0) g_bar = 0;
    if (i < HIN) {
        const float* row = Wvt + (size_t)i * (HIN + 128) + HIN;
        float u = 0.f, ub = 0.f;
        #pragma unroll 4
        for (int j = 0; j < 128; j++) { float w = row[j]; u += w * wtw[j]; ub += w * wtb[j]; }
        g_u[i] = u; g_ub[i] = ub;
    } else if (i < HIN + G4) {
        int r = i - HIN;
        int gate = ((r >> 3) & 1) * 2 + (r & 1);
        int cell = 4 * (r >> 4) + ((r >> 1) & 3);
        g_biasp[r] = bih[gate * 1024 + cell] + bhh[gate * 1024 + cell];
    } else if (i < HIN + G4 + HIN * HIN / 8) {
        int w = i - (HIN + G4);
        int r = w >> 6;
        int c8 = (w & 63) * 8;
        float4 x0 = *reinterpret_cast<const float4*>(Wvt + (size_t)r * (HIN + 128) + c8);
        float4 x1 = *reinterpret_cast<const float4*>(Wvt + (size_t)r * (HIN + 128) + c8 + 4);
        uint4 p;
        p.x = pack2(x0.x, x0.y); p.y = pack2(x0.z, x0.w);
        p.z = pack2(x1.x, x1.y); p.w = pack2(x1.z, x1.w);
        *reinterpret_cast<uint4*>(g_wvt + (size_t)r * HIN + c8) = p;
    }
}

__global__ void reduce_conv(void)
{
    int idx = blockIdx.x * 256 + threadIdx.x;
    float s = 0.f;
    #pragma unroll
    for (int z = 0; z < KSPLIT; z++) s += g_split[(size_t)z * ML * HIN + idx];
    g_vdh[idx] = __float2half_rn(s);
}

__global__ void pred_kernel(const float* __restrict__ lw,
                            const float* __restrict__ lb,
                            float* __restrict__ out)
{
    int b = blockIdx.x, tid = threadIdx.x;
    const float* hr = g_h + (size_t)b * H_SZ;
    float s = 0.f;
    for (int k = tid; k < H_SZ; k += 128) s += hr[k] * lw[k];
    __shared__ float red[128];
    red[tid] = s; __syncthreads();
    for (int off = 64; off > 0; off >>= 1) {
        if (tid < off) red[tid] += red[tid + off];
        __syncthreads();
    }
    if (tid == 0) out[b] = red[0] + lb[0];
}

// ---------------- launch -----------------------------------------------------
#define SMEM_G1   67584                          // max(pipeline 40960, epilogue)
#define SMEM_G2   ((64 + 128) * 64 * 3)          // 36864 (BM=64 1-term; epi 33792)
#define SMEM_T1   67584                          // BM=128 1-term (epilogue bound)
#define SMEM_LSTM ((32 + 64) * 128 * 3)          // 36864

extern "C" void kernel_launch(void* const* d_in, const int* in_sizes, int n_in,
                              void* d_out, int out_size)
{
    const float* v   = (const float*)d_in[0];
    const float* t   = (const float*)d_in[1];
    const float* Wd  = (const float*)d_in[2];
    const float* wtw = (const float*)d_in[3];
    const float* wtb = (const float*)d_in[4];
    const float* Wvt = (const float*)d_in[5];
    const float* Wih = (const float*)d_in[6];
    const float* Whh = (const float*)d_in[7];
    const float* bih = (const float*)d_in[8];
    const float* bhh = (const float*)d_in[9];
    const float* lw  = (const float*)d_in[10];
    const float* lb  = (const float*)d_in[11];
    float* out = (float*)d_out;

    __half *p_wd, *p_vdh, *p_wvt, *p_ih, *p_wih, *p_whh, *p_hh;
    float *p_split, *p_xg, *p_h, *p_c, *p_u, *p_ub, *p_biasp;
    cudaGetSymbolAddress((void**)&p_wd, g_wd);
    cudaGetSymbolAddress((void**)&p_vdh, g_vdh);
    cudaGetSymbolAddress((void**)&p_wvt, g_wvt);
    cudaGetSymbolAddress((void**)&p_ih, g_ih);
    cudaGetSymbolAddress((void**)&p_wih, g_wih); cudaGetSymbolAddress((void**)&p_whh, g_whh);
    cudaGetSymbolAddress((void**)&p_hh, g_hh);
    cudaGetSymbolAddress((void**)&p_split, g_split);
    cudaGetSymbolAddress((void**)&p_xg, g_xg);
    cudaGetSymbolAddress((void**)&p_h, g_h);     cudaGetSymbolAddress((void**)&p_c, g_c);
    cudaGetSymbolAddress((void**)&p_u, g_u);     cudaGetSymbolAddress((void**)&p_ub, g_ub);
    cudaGetSymbolAddress((void**)&p_biasp, g_biasp);

    cudaFuncSetAttribute(gemm1_fused, cudaFuncAttributeMaxDynamicSharedMemorySize, SMEM_G1);
    cudaFuncSetAttribute(mma_gemm<64, 128, 32, 32, 1>, cudaFuncAttributeMaxDynamicSharedMemorySize, SMEM_G2);
    cudaFuncSetAttribute(mma_gemm<128, 128, 64, 32, 2>, cudaFuncAttributeMaxDynamicSharedMemorySize, SMEM_T1);
    cudaFuncSetAttribute(lstm_persist, cudaFuncAttributeMaxDynamicSharedMemorySize, SMEM_LSTM);

    // 1) prep  2) W_down round  3) W_ih perm-round
    prep_kernel<<<(HIN + G4 + HIN * HIN / 8 + 255) / 256, 256>>>(Wvt, wtw, wtb, bih, bhh);
    conv_round<<<dim3((N_SZ / 8 + 255) / 256, HIN), 256>>>(Wd, N_SZ, N_SZ, p_wd);
    conv_perm_round<<<dim3(1, G4), 256>>>(Wih, HIN, p_wih);

    // 4) GEMM1 (LDG-reg convert, 1-term, split-K=4)
    gemm1_fused<<<dim3(HIN / 128, ML / 128, KSPLIT), 256, SMEM_G1>>>(
        v, N_SZ, p_wd, N_SZ, p_split, HIN, (size_t)ML * HIN);

    // 5) reduce partials -> vd fp16
    reduce_conv<<<(ML * HIN) / 256, 256>>>();

    // 6) GEMM2 (1-term, 64x128 tiles -> 128 CTAs)
    mma_gemm<64, 128, 32, 32, 1><<<dim3(HIN / 128, ML / 64), 256, SMEM_G2>>>(
        p_vdh, HIN, p_wvt, HIN, HIN,
        nullptr, HIN, p_ub, t, p_u, p_ih);

    // 7) GEMM3 (1-term): xg = inputs_fp16 @ Wih_perm^T + bias_perm
    mma_gemm<128, 128, 64, 32, 2><<<dim3(G4 / 128, ML / 128), 256, SMEM_T1>>>(
        p_ih, HIN, p_wih, HIN, HIN,
        p_xg, G4, p_biasp, nullptr, nullptr, nullptr);

    // 8) W_hh perm-round  9) persistent LSTM steps 0..15 (1-term h)
    conv_perm_round<<<dim3(1, G4), 256>>>(Whh, H_SZ, p_whh);
    lstm_persist<<<dim3(G4 / 64, B_SZ / 32), 128, SMEM_LSTM>>>(
        p_hh, p_whh, p_xg, p_c, p_h, p_hh);

    // 10) pred
    pred_kernel<<<B_SZ, 128>>>(lw, lb, out);
}

// round 16
// speedup vs baseline: 1.4660x; 1.0062x over previous
#include <cuda_runtime.h>
#include <cuda_fp16.h>
#include <cstdint>
#include <math.h>

// ---------------- dims ------------------------------------------------------
#define B_SZ 128
#define L_SZ 16
#define N_SZ 20000
#define HIN  512
#define H_SZ 1024
#define G4   4096
#define ML   2048
#define KSPLIT 4
// split-K chunks: 5024,5024,5024,4928 (all %32==0, sum 20000)

// ---------------- device global scratch ------------------------------------
__device__ __half g_wd[(size_t)HIN * N_SZ];       // W_down rounded fp16
__device__ float g_split[KSPLIT * ML * HIN];
__device__ __half g_vdh[ML * HIN];                // vd rounded fp16
__device__ __half g_wvt[HIN * HIN];               // W_vt[:, :512] rounded
__device__ __half g_ih[ML * HIN];                 // inputs rounded fp16
__device__ __half g_wih[G4 * HIN];                // W_ih permuted rounded
__device__ __half g_whh[(size_t)G4 * H_SZ];       // W_hh permuted rounded
__device__ float g_xg[(size_t)ML * G4];           // permuted gate cols
__device__ __half g_hh[2 * B_SZ * H_SZ];          // h rounded, double buffered
__device__ float g_h[B_SZ * H_SZ];
__device__ float g_c[B_SZ * H_SZ];
__device__ float g_u[HIN];
__device__ float g_ub[HIN];
__device__ float g_biasp[G4];
__device__ unsigned g_bar4[128];                  // 4 y-group counters, 128B apart

// ---------------- helpers ---------------------------------------------------
__device__ __forceinline__ uint32_t smem_u32(const void* p) {
    uint32_t a;
    asm("{ .reg .u64 t; cvta.to.shared.u64 t, %1; cvt.u32.u64 %0, t; }" : "=r"(a) : "l"(p));
    return a;
}
__device__ __forceinline__ void cp_async16(uint32_t dst, const void* src) {
    asm volatile("cp.async.cg.shared.global [%0], [%1], 16;" :: "r"(dst), "l"(src));
}
__device__ __forceinline__ void cp_commit() {
    asm volatile("cp.async.commit_group;" ::: "memory");
}
__device__ __forceinline__ void cp_wait1() {
    asm volatile("cp.async.wait_group 1;" ::: "memory");
}
__device__ __forceinline__ void cp_wait2() {
    asm volatile("cp.async.wait_group 2;" ::: "memory");
}
__device__ __forceinline__ void ldsm4(uint32_t* r, uint32_t addr) {
    asm volatile("ldmatrix.sync.aligned.m8n8.x4.shared.b16 {%0,%1,%2,%3}, [%4];"
        : "=r"(r[0]), "=r"(r[1]), "=r"(r[2]), "=r"(r[3]) : "r"(addr));
}
__device__ __forceinline__ void mma16816(float* c, const uint32_t* a, const uint32_t* b) {
    asm volatile("mma.sync.aligned.m16n8k16.row.col.f32.f16.f16.f32 "
        "{%0,%1,%2,%3}, {%4,%5,%6,%7}, {%8,%9}, {%0,%1,%2,%3};"
        : "+f"(c[0]), "+f"(c[1]), "+f"(c[2]), "+f"(c[3])
        : "r"(a[0]), "r"(a[1]), "r"(a[2]), "r"(a[3]), "r"(b[0]), "r"(b[1]));
}
__device__ __forceinline__ float sigf(float x) { return 1.f / (1.f + expf(-x)); }
__device__ __forceinline__ uint32_t pack2(float a, float b) {
    __half2 t; t.x = __float2half_rn(a); t.y = __float2half_rn(b);
    return *reinterpret_cast<uint32_t*>(&t);
}

// fp16 smem tile (64B rows):  16B chunk c of row r at r*64 + ((c*16) ^ (((r>>1)&3)<<4))
// fp16 smem tile (128B rows): 16B chunk c of row r at r*128 + ((c ^ (r&7))<<4)

// ---------------- GEMM1: LDG->reg fp32, convert->fp16 STS, 1-term HMMA ------
__global__ void __launch_bounds__(256, 2)
gemm1_fused(const float* __restrict__ Afp, int lda,
            const __half* __restrict__ Bm, int ldb,
            float* __restrict__ C, int ldc, size_t zstride)
{
    constexpr int BM = 128, BN = 128, WM = 64, WN = 32, MF = 4, NF = 4;
    constexpr int B16S = 128 * 64;                 // 8192 per B stage
    constexpr int OFF_AH = 3 * B16S;               // 24576; Ah[2] -> 40960 pipeline

    extern __shared__ char smem[];
    const uint32_t sbase = smem_u32(smem);
    const int tid  = threadIdx.x;
    const int lane = tid & 31;
    const int warp = tid >> 5;
    const int wm0 = (warp / (BN / WN)) * WM;
    const int wn0 = (warp % (BN / WN)) * WN;
    const int m0 = blockIdx.y * BM;
    const int n0 = blockIdx.x * BN;
    const int kbase = blockIdx.z * 5024;
    const int Kz = (blockIdx.z == 3) ? 4928 : 5024;
    C += (size_t)blockIdx.z * zstride;

    float acc[MF][NF][4];
    #pragma unroll
    for (int i = 0; i < MF; i++)
        #pragma unroll
        for (int j = 0; j < NF; j++)
            #pragma unroll
            for (int q = 0; q < 4; q++) acc[i][j][q] = 0.f;

    auto loadB = [&](int kt) {
        const int k0 = kbase + kt * 32;
        const uint32_t tb = sbase + (kt % 3) * B16S;
        #pragma unroll
        for (int q = 0; q < 2; q++) {
            const int i = tid + q * 256;
            int row = i >> 2, c = i & 3;
            uint32_t dst = tb + row * 64 + ((c * 16) ^ (((row >> 1) & 3) << 4));
            cp_async16(dst, Bm + (size_t)(n0 + row) * ldb + k0 + c * 8);
        }
    };

    float4 pa[4];
    auto ldga = [&](int kt) {
        const int k0 = kbase + kt * 32;
        #pragma unroll
        for (int q = 0; q < 4; q++) {
            const int i = tid + q * 256;
            int row = i >> 3, c = i & 7;
            pa[q] = *reinterpret_cast<const float4*>(
                Afp + (size_t)(m0 + row) * lda + k0 + c * 4);
        }
    };
    auto convert = [&](int kt) {
        char* ahb = smem + OFF_AH + (kt & 1) * 8192;
        #pragma unroll
        for (int q = 0; q < 4; q++) {
            const int i = tid + q * 256;
            int row = i >> 3, c = i & 7;
            uint2 p;
            p.x = pack2(pa[q].x, pa[q].y);
            p.y = pack2(pa[q].z, pa[q].w);
            uint32_t so = row * 64 + (((c >> 1) * 16) ^ (((row >> 1) & 3) << 4)) + (c & 1) * 8;
            *reinterpret_cast<uint2*>(ahb + so) = p;
        }
    };

    const int KT = Kz >> 5;
    loadB(0); cp_commit();
    loadB(1); cp_commit();
    ldga(0);
    convert(0);
    ldga(1);

    const int li  = lane & 15;
    const int khb = (lane >> 4) << 4;
    const int swz = ((li >> 1) & 3) << 4;

    for (int kt = 0; kt < KT; kt++) {
        if (kt + 2 < KT) loadB(kt + 2);
        cp_commit();
        cp_wait1();
        __syncthreads();

        if (kt + 1 < KT) {
            convert(kt + 1);
            if (kt + 2 < KT) ldga(kt + 2);
        }

        {
            const uint32_t tAh = sbase + OFF_AH + (kt & 1) * 8192;
            const uint32_t tB  = sbase + (kt % 3) * B16S;
            #pragma unroll
            for (int kk = 0; kk < 2; kk++) {
                const int cb = kk * 32;
                const uint32_t coff = (uint32_t)((cb + khb) ^ swz);
                uint32_t ah[MF][4];
                #pragma unroll
                for (int mf = 0; mf < MF; mf++) {
                    uint32_t ro = (wm0 + mf * 16 + li) * 64 + coff;
                    ldsm4(ah[mf], tAh + ro);
                }
                uint32_t bh[NF][2];
                #pragma unroll
                for (int nf2 = 0; nf2 < NF / 2; nf2++) {
                    uint32_t ro = (wn0 + nf2 * 16 + li) * 64 + coff;
                    uint32_t t[4];
                    ldsm4(t, tB + ro);
                    bh[2 * nf2][0] = t[0]; bh[2 * nf2][1] = t[2];
                    bh[2 * nf2 + 1][0] = t[1]; bh[2 * nf2 + 1][1] = t[3];
                }
                #pragma unroll
                for (int mf = 0; mf < MF; mf++)
                    #pragma unroll
                    for (int nf = 0; nf < NF; nf++)
                        mma16816(acc[mf][nf], ah[mf], bh[nf]);
            }
        }
        __syncthreads();
    }

    float* st = reinterpret_cast<float*>(smem) + warp * (WM * 33);
    #pragma unroll
    for (int mf = 0; mf < MF; mf++)
        #pragma unroll
        for (int nf = 0; nf < NF; nf++)
            #pragma unroll
            for (int i = 0; i < 2; i++) {
                int r = mf * 16 + (lane >> 2) + 8 * i;
                int c = nf * 8 + 2 * (lane & 3);
                st[r * 33 + c]     = acc[mf][nf][2 * i];
                st[r * 33 + c + 1] = acc[mf][nf][2 * i + 1];
            }
    __syncwarp();
    #pragma unroll
    for (int rr = lane; rr < WM; rr += 32) {
        const int m = m0 + wm0 + rr;
        #pragma unroll
        for (int c4 = 0; c4 < WN; c4 += 4) {
            float4 v;
            v.x = st[rr * 33 + c4];     v.y = st[rr * 33 + c4 + 1];
            v.z = st[rr * 33 + c4 + 2]; v.w = st[rr * 33 + c4 + 3];
            *reinterpret_cast<float4*>(C + (size_t)m * ldc + n0 + wn0 + c4) = v;
        }
    }
}

// ---------------- generic fp16 GEMM (modes 1,2; 1-term A) --------------------
template<int BM, int BN, int WM, int WN, int MODE>
__global__ void __launch_bounds__((BM / WM) * (BN / WN) * 32)
mma_gemm(const __half* __restrict__ Ah, int lda,
         const __half* __restrict__ Bm, int ldb, int K,
         float* __restrict__ C, int ldc,
         const float* __restrict__ bias,
         const float* __restrict__ srow, const float* __restrict__ ucol,
         __half* __restrict__ Ch)
{
    constexpr int NT = (BM / WM) * (BN / WN) * 32;
    constexpr int MF = WM / 16;
    constexpr int NF = WN / 8;
    constexpr int STAGE = (BM + BN) * 64;
    constexpr int CHA = BM * 4;
    constexpr int CHB = BN * 4;
    constexpr int CHT = CHA + CHB;

    extern __shared__ char smem[];
    const uint32_t sbase = smem_u32(smem);
    const int tid  = threadIdx.x;
    const int lane = tid & 31;
    const int warp = tid >> 5;
    const int wm0 = (warp / (BN / WN)) * WM;
    const int wn0 = (warp % (BN / WN)) * WN;
    const int m0 = blockIdx.y * BM;
    const int n0 = blockIdx.x * BN;

    float acc[MF][NF][4];
    #pragma unroll
    for (int i = 0; i < MF; i++)
        #pragma unroll
        for (int j = 0; j < NF; j++)
            #pragma unroll
            for (int q = 0; q < 4; q++) acc[i][j][q] = 0.f;

    auto load_stage = [&](int kt, int s) {
        const int k0 = kt * 32;
        const uint32_t tb = sbase + s * STAGE;
        #pragma unroll
        for (int q = 0; q < CHT / NT; q++) {
            const int i = tid + q * NT;
            const __half* src;
            int toff, rr;
            if (i < CHA) {
                rr = i >> 2; src = Ah + (size_t)(m0 + rr) * lda; toff = 0;
            } else {
                int j = i - CHA; rr = j >> 2;
                src = Bm + (size_t)(n0 + rr) * ldb; toff = BM * 64;
            }
            const int c = i & 3;
            uint32_t dst = tb + toff + rr * 64 + ((c * 16) ^ (((rr >> 1) & 3) << 4));
            cp_async16(dst, src + k0 + c * 8);
        }
    };

    const int KT = K >> 5;
    load_stage(0, 0); cp_commit();
    load_stage(1, 1); cp_commit();

    const int li  = lane & 15;
    const int khb = (lane >> 4) << 4;
    const int swz = ((li >> 1) & 3) << 4;

    for (int kt = 0; kt < KT; kt++) {
        const int s = kt % 3;
        if (kt + 2 < KT) load_stage(kt + 2, (kt + 2) % 3);
        cp_commit();
        cp_wait2();
        __syncthreads();

        const uint32_t tA = sbase + s * STAGE;
        const uint32_t tB = tA + BM * 64;

        #pragma unroll
        for (int kk = 0; kk < 2; kk++) {
            const int cb = kk * 32;
            const uint32_t coff = (uint32_t)((cb + khb) ^ swz);
            uint32_t ah[MF][4];
            #pragma unroll
            for (int mf = 0; mf < MF; mf++) {
                uint32_t ro = (wm0 + mf * 16 + li) * 64 + coff;
                ldsm4(ah[mf], tA + ro);
            }
            uint32_t bh[NF][2];
            #pragma unroll
            for (int nf2 = 0; nf2 < NF / 2; nf2++) {
                uint32_t ro = (wn0 + nf2 * 16 + li) * 64 + coff;
                uint32_t t[4];
                ldsm4(t, tB + ro);
                bh[2 * nf2][0] = t[0]; bh[2 * nf2][1] = t[2];
                bh[2 * nf2 + 1][0] = t[1]; bh[2 * nf2 + 1][1] = t[3];
            }
            #pragma unroll
            for (int mf = 0; mf < MF; mf++)
                #pragma unroll
                for (int nf = 0; nf < NF; nf++)
                    mma16816(acc[mf][nf], ah[mf], bh[nf]);
        }
        __syncthreads();
    }

    float* st = reinterpret_cast<float*>(smem) + warp * (WM * 33);
    #pragma unroll
    for (int mf = 0; mf < MF; mf++)
        #pragma unroll
        for (int nf = 0; nf < NF; nf++)
            #pragma unroll
            for (int i = 0; i < 2; i++) {
                int r = mf * 16 + (lane >> 2) + 8 * i;
                int c = nf * 8 + 2 * (lane & 3);
                st[r * 33 + c]     = acc[mf][nf][2 * i];
                st[r * 33 + c + 1] = acc[mf][nf][2 * i + 1];
            }
    __syncwarp();
    #pragma unroll
    for (int rr = lane; rr < WM; rr += 32) {
        const int m = m0 + wm0 + rr;
        const int nbase = n0 + wn0;
        if (MODE == 1) {
            const float tm = srow[m];
            #pragma unroll
            for (int c = 0; c < WN; c += 2) {
                int n = nbase + c;
                float v0 = st[rr * 33 + c]     + tm * ucol[n]     + bias[n];
                float v1 = st[rr * 33 + c + 1] + tm * ucol[n + 1] + bias[n + 1];
                __half2 ph;
                ph.x = __float2half_rn(v0); ph.y = __float2half_rn(v1);
                *reinterpret_cast<__half2*>(Ch + (size_t)m * ldc + n) = ph;
            }
        } else {
            #pragma unroll
            for (int c4 = 0; c4 < WN; c4 += 4) {
                float4 v;
                v.x = st[rr * 33 + c4];
                v.y = st[rr * 33 + c4 + 1];
                v.z = st[rr * 33 + c4 + 2];
                v.w = st[rr * 33 + c4 + 3];
                int n = nbase + c4;
                v.x += bias[n]; v.y += bias[n + 1];
                v.z += bias[n + 2]; v.w += bias[n + 3];
                *reinterpret_cast<float4*>(C + (size_t)m * ldc + nbase + c4) = v;
            }
        }
    }
}

// ---------------- persistent fused LSTM, BK=64, 1-term h, y-group barriers ---
// CTA (x,y) step l depends only on step l-1 outputs of CTAs (*, y):
// A rows m in [32y, 32y+32) are produced by y-group; c-state is CTA-private.
__global__ void __launch_bounds__(128)
lstm_persist(const __half* __restrict__ hhb,
             const __half* __restrict__ Bm,
             const float* __restrict__ xg, float* __restrict__ cstate,
             float* __restrict__ houtf,
             __half* __restrict__ hhw)
{
    constexpr int BM = 32, BN = 64, NT = 128, NF = 4;
    constexpr int STAGE = (BM + BN) * 128;       // 12288
    constexpr int CHA = BM * 8, CHB = BN * 8, CHT = CHA + CHB;   // 768

    extern __shared__ char smem[];
    const uint32_t sbase = smem_u32(smem);
    const int tid  = threadIdx.x;
    const int lane = tid & 31;
    const int warp = tid >> 5;
    const int wm0 = (warp >> 1) * 16;
    const int wn0 = (warp & 1) * 32;
    const int m0 = blockIdx.y * BM;
    const int n0 = blockIdx.x * BN;
    const int li  = lane & 15;
    const int qhb = lane >> 4;
    unsigned* ybar = &g_bar4[blockIdx.y * 32];   // 128B-separated counters

    auto dev_barrier = [&](unsigned sv) {
        __threadfence();
        __syncthreads();
        if (tid == 0) {
            atomicAdd(ybar, 1u);
            volatile unsigned* vb = ybar;
            const unsigned target = 64u * sv;
            while (*vb < target) { }
        }
        __syncthreads();
    };

    // ---- step 0: h=c=0, gates = xg row ----
    {
        __half* Oh = hhw;
        const float* xgl = xg;
        #pragma unroll
        for (int qsel = 0; qsel < NF / 2; qsel++) {
            const int nb = n0 + wn0 + qsel * 16;
            const int a  = lane & 3;
            const int j  = 4 * (nb >> 4) + a;
            #pragma unroll
            for (int i = 0; i < 2; i++) {
                const int m = m0 + wm0 + (lane >> 2) + 8 * i;
                const float* xrow = xgl + (size_t)m * (L_SZ * G4);
                float2 xif = *reinterpret_cast<const float2*>(xrow + nb + 2 * a);
                float2 xgo = *reinterpret_cast<const float2*>(xrow + nb + 8 + 2 * a);
                float ig = sigf(xif.x);
                float gg = tanhf(xgo.x), og = sigf(xgo.y);
                const int gi = (m << 10) + j;
                float cv = ig * gg;
                cstate[gi] = cv;
                float hv = og * tanhf(cv);
                Oh[gi] = __float2half_rn(hv);
            }
        }
        dev_barrier(1u);
    }

    for (int l = 1; l < L_SZ; l++) {
        const __half* Ah = hhb + (size_t)((l + 1) & 1) * (B_SZ * H_SZ);
        __half* Oh = hhw + (size_t)(l & 1) * (B_SZ * H_SZ);
        const float* xgl = xg + (size_t)l * G4;

        float acc[NF][4];
        #pragma unroll
        for (int j = 0; j < NF; j++)
            #pragma unroll
            for (int q = 0; q < 4; q++) acc[j][q] = 0.f;

        auto load_stage = [&](int kt, int s) {
            const int k0 = kt * 64;
            const uint32_t tb = sbase + s * STAGE;
            #pragma unroll
            for (int q = 0; q < CHT / NT; q++) {
                const int i = tid + q * NT;
                const __half* src;
                int toff, rr;
                if (i < CHA) {
                    rr = i >> 3; src = Ah + (size_t)(m0 + rr) * H_SZ; toff = 0;
                } else {
                    int j = i - CHA; rr = j >> 3;
                    src = Bm + (size_t)(n0 + rr) * H_SZ; toff = BM * 128;
                }
                const int c = i & 7;
                uint32_t dst = tb + toff + rr * 128 + ((c ^ (rr & 7)) << 4);
                cp_async16(dst, src + k0 + c * 8);
            }
        };

        const int KT = H_SZ >> 6;   // 16
        load_stage(0, 0); cp_commit();
        load_stage(1, 1); cp_commit();

        for (int kt = 0; kt < KT; kt++) {
            const int s = kt % 3;
            if (kt + 2 < KT) load_stage(kt + 2, (kt + 2) % 3);
            cp_commit();
            cp_wait2();
            __syncthreads();

            const uint32_t tA = sbase + s * STAGE;
            const uint32_t tB = tA + BM * 128;

            #pragma unroll
            for (int kk = 0; kk < 4; kk++) {
                const int q = kk * 2 + qhb;
                const uint32_t sw = (uint32_t)((q ^ (li & 7)) << 4);
                uint32_t ah[4];
                {
                    uint32_t ro = (wm0 + li) * 128 + sw;
                    ldsm4(ah, tA + ro);
                }
                uint32_t bh[NF][2];
                #pragma unroll
                for (int nf2 = 0; nf2 < NF / 2; nf2++) {
                    uint32_t ro = (wn0 + nf2 * 16 + li) * 128 + sw;
                    uint32_t t[4];
                    ldsm4(t, tB + ro);
                    bh[2 * nf2][0] = t[0]; bh[2 * nf2][1] = t[2];
                    bh[2 * nf2 + 1][0] = t[1]; bh[2 * nf2 + 1][1] = t[3];
                }
                #pragma unroll
                for (int nf = 0; nf < NF; nf++)
                    mma16816(acc[nf], ah, bh[nf]);
            }
            __syncthreads();
        }

        // fused gate nonlinearity + state update
        #pragma unroll
        for (int qsel = 0; qsel < NF / 2; qsel++) {
            const int nb = n0 + wn0 + qsel * 16;
            const int a  = lane & 3;
            const int j  = 4 * (nb >> 4) + a;
            #pragma unroll
            for (int i = 0; i < 2; i++) {
                const int m = m0 + wm0 + (lane >> 2) + 8 * i;
                const float* xrow = xgl + (size_t)m * (L_SZ * G4);
                float2 xif = *reinterpret_cast<const float2*>(xrow + nb + 2 * a);
                float2 xgo = *reinterpret_cast<const float2*>(xrow + nb + 8 + 2 * a);
                float xi = acc[2 * qsel][2 * i]         + xif.x;
                float xf = acc[2 * qsel][2 * i + 1]     + xif.y;
                float xgv = acc[2 * qsel + 1][2 * i]    + xgo.x;
                float xo = acc[2 * qsel + 1][2 * i + 1] + xgo.y;
                float ig = sigf(xi), fg = sigf(xf);
                float gg = tanhf(xgv), og = sigf(xo);
                const int gi = (m << 10) + j;
                float cv = fg * cstate[gi] + ig * gg;
                cstate[gi] = cv;
                float hv = og * tanhf(cv);
                houtf[gi] = hv;
                Oh[gi] = __float2half_rn(hv);
            }
        }

        dev_barrier((unsigned)(l + 1));
    }
}

// ---------------- converts ---------------------------------------------------
// 16 floats/thread (4 independent LDG.128): MLP=4
__global__ void conv_round(const float* __restrict__ src, int C, int srcld,
                           __half* __restrict__ dst)
{
    int c16 = (blockIdx.x * blockDim.x + threadIdx.x) * 16;
    int r = blockIdx.y;
    if (c16 >= C) return;
    const float* s = src + (size_t)r * srcld + c16;
    float4 x0 = *reinterpret_cast<const float4*>(s);
    float4 x1 = *reinterpret_cast<const float4*>(s + 4);
    float4 x2 = *reinterpret_cast<const float4*>(s + 8);
    float4 x3 = *reinterpret_cast<const float4*>(s + 12);
    uint4 p0, p1;
    p0.x = pack2(x0.x, x0.y); p0.y = pack2(x0.z, x0.w);
    p0.z = pack2(x1.x, x1.y); p0.w = pack2(x1.z, x1.w);
    p1.x = pack2(x2.x, x2.y); p1.y = pack2(x2.z, x2.w);
    p1.z = pack2(x3.x, x3.y); p1.w = pack2(x3.z, x3.w);
    __half* d = dst + (size_t)r * C + c16;
    *reinterpret_cast<uint4*>(d)     = p0;
    *reinterpret_cast<uint4*>(d + 8) = p1;
}

__global__ void conv_perm_round(const float* __restrict__ src, int cols,
                                __half* __restrict__ dst)
{
    int c8 = (blockIdx.x * blockDim.x + threadIdx.x) * 8;
    int r = blockIdx.y;
    if (c8 >= cols) return;
    int gate = ((r >> 3) & 1) * 2 + (r & 1);
    int cell = 4 * (r >> 4) + ((r >> 1) & 3);
    int orig = gate * 1024 + cell;
    float4 x0 = *reinterpret_cast<const float4*>(src + (size_t)orig * cols + c8);
    float4 x1 = *reinterpret_cast<const float4*>(src + (size_t)orig * cols + c8 + 4);
    uint4 p;
    p.x = pack2(x0.x, x0.y); p.y = pack2(x0.z, x0.w);
    p.z = pack2(x1.x, x1.y); p.w = pack2(x1.z, x1.w);
    *reinterpret_cast<uint4*>(dst + (size_t)r * cols + c8) = p;
}

__global__ void prep_kernel(const float* __restrict__ Wvt,
                            const float* __restrict__ wtw,
                            const float* __restrict__ wtb,
                            const float* __restrict__ bih,
                            const float* __restrict__ bhh)
{
    int i = blockIdx.x * blockDim.x + threadIdx.x;
    if (i < 128) g_bar4[i] = 0;
    if (i < HIN) {
        const float* row = Wvt + (size_t)i * (HIN + 128) + HIN;
        float u = 0.f, ub = 0.f;
        #pragma unroll 4
        for (int j = 0; j < 128; j++) { float w = row[j]; u += w * wtw[j]; ub += w * wtb[j]; }
        g_u[i] = u; g_ub[i] = ub;
    } else if (i < HIN + G4) {
        int r = i - HIN;
        int gate = ((r >> 3) & 1) * 2 + (r & 1);
        int cell = 4 * (r >> 4) + ((r >> 1) & 3);
        g_biasp[r] = bih[gate * 1024 + cell] + bhh[gate * 1024 + cell];
    } else if (i < HIN + G4 + HIN * HIN / 8) {
        int w = i - (HIN + G4);
        int r = w >> 6;
        int c8 = (w & 63) * 8;
        float4 x0 = *reinterpret_cast<const float4*>(Wvt + (size_t)r * (HIN + 128) + c8);
        float4 x1 = *reinterpret_cast<const float4*>(Wvt + (size_t)r * (HIN + 128) + c8 + 4);
        uint4 p;
        p.x = pack2(x0.x, x0.y); p.y = pack2(x0.z, x0.w);
        p.z = pack2(x1.x, x1.y); p.w = pack2(x1.z, x1.w);
        *reinterpret_cast<uint4*>(g_wvt + (size_t)r * HIN + c8) = p;
    }
}

__global__ void reduce_conv(void)
{
    int idx = blockIdx.x * 256 + threadIdx.x;
    float s = 0.f;
    #pragma unroll
    for (int z = 0; z < KSPLIT; z++) s += g_split[(size_t)z * ML * HIN + idx];
    g_vdh[idx] = __float2half_rn(s);
}

__global__ void pred_kernel(const float* __restrict__ lw,
                            const float* __restrict__ lb,
                            float* __restrict__ out)
{
    int b = blockIdx.x, tid = threadIdx.x;
    const float* hr = g_h + (size_t)b * H_SZ;
    float s = 0.f;
    for (int k = tid; k < H_SZ; k += 128) s += hr[k] * lw[k];
    __shared__ float red[128];
    red[tid] = s; __syncthreads();
    for (int off = 64; off > 0; off >>= 1) {
        if (tid < off) red[tid] += red[tid + off];
        __syncthreads();
    }
    if (tid == 0) out[b] = red[0] + lb[0];
}

// ---------------- launch -----------------------------------------------------
#define SMEM_G1   67584                          // max(pipeline 40960, epilogue)
#define SMEM_G2   ((64 + 128) * 64 * 3)          // 36864 (BM=64 1-term)
#define SMEM_T1   67584                          // BM=128 1-term (epilogue bound)
#define SMEM_LSTM ((32 + 64) * 128 * 3)          // 36864

extern "C" void kernel_launch(void* const* d_in, const int* in_sizes, int n_in,
                              void* d_out, int out_size)
{
    const float* v   = (const float*)d_in[0];
    const float* t   = (const float*)d_in[1];
    const float* Wd  = (const float*)d_in[2];
    const float* wtw = (const float*)d_in[3];
    const float* wtb = (const float*)d_in[4];
    const float* Wvt = (const float*)d_in[5];
    const float* Wih = (const float*)d_in[6];
    const float* Whh = (const float*)d_in[7];
    const float* bih = (const float*)d_in[8];
    const float* bhh = (const float*)d_in[9];
    const float* lw  = (const float*)d_in[10];
    const float* lb  = (const float*)d_in[11];
    float* out = (float*)d_out;

    __half *p_wd, *p_vdh, *p_wvt, *p_ih, *p_wih, *p_whh, *p_hh;
    float *p_split, *p_xg, *p_h, *p_c, *p_u, *p_ub, *p_biasp;
    cudaGetSymbolAddress((void**)&p_wd, g_wd);
    cudaGetSymbolAddress((void**)&p_vdh, g_vdh);
    cudaGetSymbolAddress((void**)&p_wvt, g_wvt);
    cudaGetSymbolAddress((void**)&p_ih, g_ih);
    cudaGetSymbolAddress((void**)&p_wih, g_wih); cudaGetSymbolAddress((void**)&p_whh, g_whh);
    cudaGetSymbolAddress((void**)&p_hh, g_hh);
    cudaGetSymbolAddress((void**)&p_split, g_split);
    cudaGetSymbolAddress((void**)&p_xg, g_xg);
    cudaGetSymbolAddress((void**)&p_h, g_h);     cudaGetSymbolAddress((void**)&p_c, g_c);
    cudaGetSymbolAddress((void**)&p_u, g_u);     cudaGetSymbolAddress((void**)&p_ub, g_ub);
    cudaGetSymbolAddress((void**)&p_biasp, g_biasp);

    cudaFuncSetAttribute(gemm1_fused, cudaFuncAttributeMaxDynamicSharedMemorySize, SMEM_G1);
    cudaFuncSetAttribute(mma_gemm<64, 128, 32, 32, 1>, cudaFuncAttributeMaxDynamicSharedMemorySize, SMEM_G2);
    cudaFuncSetAttribute(mma_gemm<128, 128, 64, 32, 2>, cudaFuncAttributeMaxDynamicSharedMemorySize, SMEM_T1);
    cudaFuncSetAttribute(lstm_persist, cudaFuncAttributeMaxDynamicSharedMemorySize, SMEM_LSTM);

    // 1) prep  2) W_down round  3) W_ih perm-round
    prep_kernel<<<(HIN + G4 + HIN * HIN / 8 + 255) / 256, 256>>>(Wvt, wtw, wtb, bih, bhh);
    conv_round<<<dim3((N_SZ / 16 + 255) / 256, HIN), 256>>>(Wd, N_SZ, N_SZ, p_wd);
    conv_perm_round<<<dim3(1, G4), 256>>>(Wih, HIN, p_wih);

    // 4) GEMM1 (LDG-reg convert, 1-term, split-K=4)
    gemm1_fused<<<dim3(HIN / 128, ML / 128, KSPLIT), 256, SMEM_G1>>>(
        v, N_SZ, p_wd, N_SZ, p_split, HIN, (size_t)ML * HIN);

    // 5) reduce partials -> vd fp16
    reduce_conv<<<(ML * HIN) / 256, 256>>>();

    // 6) GEMM2 (1-term, 64x128 tiles -> 128 CTAs)
    mma_gemm<64, 128, 32, 32, 1><<<dim3(HIN / 128, ML / 64), 256, SMEM_G2>>>(
        p_vdh, HIN, p_wvt, HIN, HIN,
        nullptr, HIN, p_ub, t, p_u, p_ih);

    // 7) GEMM3 (1-term): xg = inputs_fp16 @ Wih_perm^T + bias_perm
    mma_gemm<128, 128, 64, 32, 2><<<dim3(G4 / 128, ML / 128), 256, SMEM_T1>>>(
        p_ih, HIN, p_wih, HIN, HIN,
        p_xg, G4, p_biasp, nullptr, nullptr, nullptr);

    // 8) W_hh perm-round  9) persistent LSTM steps 0..15 (y-group barriers)
    conv_perm_round<<<dim3(1, G4), 256>>>(Whh, H_SZ, p_whh);
    lstm_persist<<<dim3(G4 / 64, B_SZ / 32), 128, SMEM_LSTM>>>(
        p_hh, p_whh, p_xg, p_c, p_h, p_hh);

    // 10) pred
    pred_kernel<<<B_SZ, 128>>>(lw, lb, out);
}

// round 17
// speedup vs baseline: 1.4752x; 1.0063x over previous
#include <cuda_runtime.h>
#include <cuda_fp16.h>
#include <cstdint>
#include <math.h>

// ---------------- dims ------------------------------------------------------
#define B_SZ 128
#define L_SZ 16
#define N_SZ 20000
#define HIN  512
#define H_SZ 1024
#define G4   4096
#define ML   2048
#define KSPLIT 4
// split-K chunks: 5024,5024,5024,4928 (all %32==0, sum 20000)

// ---------------- device global scratch ------------------------------------
__device__ __half g_wd[(size_t)HIN * N_SZ];       // W_down rounded fp16
__device__ float g_split[KSPLIT * ML * HIN];
__device__ __half g_vdh[ML * HIN];                // vd rounded fp16
__device__ __half g_wvt[HIN * HIN];               // W_vt[:, :512] rounded
__device__ __half g_ih[ML * HIN];                 // inputs rounded fp16
__device__ __half g_wih[G4 * HIN];                // W_ih permuted rounded
__device__ __half g_whh[(size_t)G4 * H_SZ];       // W_hh permuted rounded
__device__ float g_xg[(size_t)ML * G4];           // permuted gate cols
__device__ __half g_hh[2 * B_SZ * H_SZ];          // h rounded, double buffered
__device__ float g_h[B_SZ * H_SZ];
__device__ float g_c[B_SZ * H_SZ];
__device__ float g_u[HIN];
__device__ float g_ub[HIN];
__device__ float g_biasp[G4];
__device__ unsigned g_bar4[128];                  // y-group counters, 128B apart

// ---------------- helpers ---------------------------------------------------
__device__ __forceinline__ uint32_t smem_u32(const void* p) {
    uint32_t a;
    asm("{ .reg .u64 t; cvta.to.shared.u64 t, %1; cvt.u32.u64 %0, t; }" : "=r"(a) : "l"(p));
    return a;
}
__device__ __forceinline__ void cp_async16(uint32_t dst, const void* src) {
    asm volatile("cp.async.cg.shared.global [%0], [%1], 16;" :: "r"(dst), "l"(src));
}
__device__ __forceinline__ void cp_commit() {
    asm volatile("cp.async.commit_group;" ::: "memory");
}
__device__ __forceinline__ void cp_wait0() {
    asm volatile("cp.async.wait_group 0;" ::: "memory");
}
__device__ __forceinline__ void cp_wait1() {
    asm volatile("cp.async.wait_group 1;" ::: "memory");
}
__device__ __forceinline__ void cp_wait2() {
    asm volatile("cp.async.wait_group 2;" ::: "memory");
}
__device__ __forceinline__ void ldsm4(uint32_t* r, uint32_t addr) {
    asm volatile("ldmatrix.sync.aligned.m8n8.x4.shared.b16 {%0,%1,%2,%3}, [%4];"
        : "=r"(r[0]), "=r"(r[1]), "=r"(r[2]), "=r"(r[3]) : "r"(addr));
}
__device__ __forceinline__ void mma16816(float* c, const uint32_t* a, const uint32_t* b) {
    asm volatile("mma.sync.aligned.m16n8k16.row.col.f32.f16.f16.f32 "
        "{%0,%1,%2,%3}, {%4,%5,%6,%7}, {%8,%9}, {%0,%1,%2,%3};"
        : "+f"(c[0]), "+f"(c[1]), "+f"(c[2]), "+f"(c[3])
        : "r"(a[0]), "r"(a[1]), "r"(a[2]), "r"(a[3]), "r"(b[0]), "r"(b[1]));
}
__device__ __forceinline__ float sigf(float x) { return 1.f / (1.f + expf(-x)); }
__device__ __forceinline__ uint32_t pack2(float a, float b) {
    __half2 t; t.x = __float2half_rn(a); t.y = __float2half_rn(b);
    return *reinterpret_cast<uint32_t*>(&t);
}

// fp16 smem tile (64B rows):  16B chunk c of row r at r*64 + ((c*16) ^ (((r>>1)&3)<<4))
// fp16 smem tile (128B rows): 16B chunk c of row r at r*128 + ((c ^ (r&7))<<4)

// ---------------- GEMM1: LDG->reg fp32, convert->fp16 STS, 1-term HMMA ------
__global__ void __launch_bounds__(256, 2)
gemm1_fused(const float* __restrict__ Afp, int lda,
            const __half* __restrict__ Bm, int ldb,
            float* __restrict__ C, int ldc, size_t zstride)
{
    constexpr int BM = 128, BN = 128, WM = 64, WN = 32, MF = 4, NF = 4;
    constexpr int B16S = 128 * 64;                 // 8192 per B stage
    constexpr int OFF_AH = 3 * B16S;               // 24576; Ah[2] -> 40960 pipeline

    extern __shared__ char smem[];
    const uint32_t sbase = smem_u32(smem);
    const int tid  = threadIdx.x;
    const int lane = tid & 31;
    const int warp = tid >> 5;
    const int wm0 = (warp / (BN / WN)) * WM;
    const int wn0 = (warp % (BN / WN)) * WN;
    const int m0 = blockIdx.y * BM;
    const int n0 = blockIdx.x * BN;
    const int kbase = blockIdx.z * 5024;
    const int Kz = (blockIdx.z == 3) ? 4928 : 5024;
    C += (size_t)blockIdx.z * zstride;

    float acc[MF][NF][4];
    #pragma unroll
    for (int i = 0; i < MF; i++)
        #pragma unroll
        for (int j = 0; j < NF; j++)
            #pragma unroll
            for (int q = 0; q < 4; q++) acc[i][j][q] = 0.f;

    auto loadB = [&](int kt) {
        const int k0 = kbase + kt * 32;
        const uint32_t tb = sbase + (kt % 3) * B16S;
        #pragma unroll
        for (int q = 0; q < 2; q++) {
            const int i = tid + q * 256;
            int row = i >> 2, c = i & 3;
            uint32_t dst = tb + row * 64 + ((c * 16) ^ (((row >> 1) & 3) << 4));
            cp_async16(dst, Bm + (size_t)(n0 + row) * ldb + k0 + c * 8);
        }
    };

    float4 pa[4];
    auto ldga = [&](int kt) {
        const int k0 = kbase + kt * 32;
        #pragma unroll
        for (int q = 0; q < 4; q++) {
            const int i = tid + q * 256;
            int row = i >> 3, c = i & 7;
            pa[q] = *reinterpret_cast<const float4*>(
                Afp + (size_t)(m0 + row) * lda + k0 + c * 4);
        }
    };
    auto convert = [&](int kt) {
        char* ahb = smem + OFF_AH + (kt & 1) * 8192;
        #pragma unroll
        for (int q = 0; q < 4; q++) {
            const int i = tid + q * 256;
            int row = i >> 3, c = i & 7;
            uint2 p;
            p.x = pack2(pa[q].x, pa[q].y);
            p.y = pack2(pa[q].z, pa[q].w);
            uint32_t so = row * 64 + (((c >> 1) * 16) ^ (((row >> 1) & 3) << 4)) + (c & 1) * 8;
            *reinterpret_cast<uint2*>(ahb + so) = p;
        }
    };

    const int KT = Kz >> 5;
    loadB(0); cp_commit();
    loadB(1); cp_commit();
    ldga(0);
    convert(0);
    ldga(1);

    const int li  = lane & 15;
    const int khb = (lane >> 4) << 4;
    const int swz = ((li >> 1) & 3) << 4;

    for (int kt = 0; kt < KT; kt++) {
        if (kt + 2 < KT) loadB(kt + 2);
        cp_commit();
        cp_wait1();
        __syncthreads();

        if (kt + 1 < KT) {
            convert(kt + 1);
            if (kt + 2 < KT) ldga(kt + 2);
        }

        {
            const uint32_t tAh = sbase + OFF_AH + (kt & 1) * 8192;
            const uint32_t tB  = sbase + (kt % 3) * B16S;
            #pragma unroll
            for (int kk = 0; kk < 2; kk++) {
                const int cb = kk * 32;
                const uint32_t coff = (uint32_t)((cb + khb) ^ swz);
                uint32_t ah[MF][4];
                #pragma unroll
                for (int mf = 0; mf < MF; mf++) {
                    uint32_t ro = (wm0 + mf * 16 + li) * 64 + coff;
                    ldsm4(ah[mf], tAh + ro);
                }
                uint32_t bh[NF][2];
                #pragma unroll
                for (int nf2 = 0; nf2 < NF / 2; nf2++) {
                    uint32_t ro = (wn0 + nf2 * 16 + li) * 64 + coff;
                    uint32_t t[4];
                    ldsm4(t, tB + ro);
                    bh[2 * nf2][0] = t[0]; bh[2 * nf2][1] = t[2];
                    bh[2 * nf2 + 1][0] = t[1]; bh[2 * nf2 + 1][1] = t[3];
                }
                #pragma unroll
                for (int mf = 0; mf < MF; mf++)
                    #pragma unroll
                    for (int nf = 0; nf < NF; nf++)
                        mma16816(acc[mf][nf], ah[mf], bh[nf]);
            }
        }
        __syncthreads();
    }

    float* st = reinterpret_cast<float*>(smem) + warp * (WM * 33);
    #pragma unroll
    for (int mf = 0; mf < MF; mf++)
        #pragma unroll
        for (int nf = 0; nf < NF; nf++)
            #pragma unroll
            for (int i = 0; i < 2; i++) {
                int r = mf * 16 + (lane >> 2) + 8 * i;
                int c = nf * 8 + 2 * (lane & 3);
                st[r * 33 + c]     = acc[mf][nf][2 * i];
                st[r * 33 + c + 1] = acc[mf][nf][2 * i + 1];
            }
    __syncwarp();
    #pragma unroll
    for (int rr = lane; rr < WM; rr += 32) {
        const int m = m0 + wm0 + rr;
        #pragma unroll
        for (int c4 = 0; c4 < WN; c4 += 4) {
            float4 v;
            v.x = st[rr * 33 + c4];     v.y = st[rr * 33 + c4 + 1];
            v.z = st[rr * 33 + c4 + 2]; v.w = st[rr * 33 + c4 + 3];
            *reinterpret_cast<float4*>(C + (size_t)m * ldc + n0 + wn0 + c4) = v;
        }
    }
}

// ---------------- generic fp16 GEMM (modes 1,2; 1-term A) --------------------
template<int BM, int BN, int WM, int WN, int MODE>
__global__ void __launch_bounds__((BM / WM) * (BN / WN) * 32)
mma_gemm(const __half* __restrict__ Ah, int lda,
         const __half* __restrict__ Bm, int ldb, int K,
         float* __restrict__ C, int ldc,
         const float* __restrict__ bias,
         const float* __restrict__ srow, const float* __restrict__ ucol,
         __half* __restrict__ Ch)
{
    constexpr int NT = (BM / WM) * (BN / WN) * 32;
    constexpr int MF = WM / 16;
    constexpr int NF = WN / 8;
    constexpr int STAGE = (BM + BN) * 64;
    constexpr int CHA = BM * 4;
    constexpr int CHB = BN * 4;
    constexpr int CHT = CHA + CHB;

    extern __shared__ char smem[];
    const uint32_t sbase = smem_u32(smem);
    const int tid  = threadIdx.x;
    const int lane = tid & 31;
    const int warp = tid >> 5;
    const int wm0 = (warp / (BN / WN)) * WM;
    const int wn0 = (warp % (BN / WN)) * WN;
    const int m0 = blockIdx.y * BM;
    const int n0 = blockIdx.x * BN;

    float acc[MF][NF][4];
    #pragma unroll
    for (int i = 0; i < MF; i++)
        #pragma unroll
        for (int j = 0; j < NF; j++)
            #pragma unroll
            for (int q = 0; q < 4; q++) acc[i][j][q] = 0.f;

    auto load_stage = [&](int kt, int s) {
        const int k0 = kt * 32;
        const uint32_t tb = sbase + s * STAGE;
        #pragma unroll
        for (int q = 0; q < CHT / NT; q++) {
            const int i = tid + q * NT;
            const __half* src;
            int toff, rr;
            if (i < CHA) {
                rr = i >> 2; src = Ah + (size_t)(m0 + rr) * lda; toff = 0;
            } else {
                int j = i - CHA; rr = j >> 2;
                src = Bm + (size_t)(n0 + rr) * ldb; toff = BM * 64;
            }
            const int c = i & 3;
            uint32_t dst = tb + toff + rr * 64 + ((c * 16) ^ (((rr >> 1) & 3) << 4));
            cp_async16(dst, src + k0 + c * 8);
        }
    };

    const int KT = K >> 5;
    load_stage(0, 0); cp_commit();
    load_stage(1, 1); cp_commit();

    const int li  = lane & 15;
    const int khb = (lane >> 4) << 4;
    const int swz = ((li >> 1) & 3) << 4;

    for (int kt = 0; kt < KT; kt++) {
        const int s = kt % 3;
        if (kt + 2 < KT) load_stage(kt + 2, (kt + 2) % 3);
        cp_commit();
        cp_wait2();
        __syncthreads();

        const uint32_t tA = sbase + s * STAGE;
        const uint32_t tB = tA + BM * 64;

        #pragma unroll
        for (int kk = 0; kk < 2; kk++) {
            const int cb = kk * 32;
            const uint32_t coff = (uint32_t)((cb + khb) ^ swz);
            uint32_t ah[MF][4];
            #pragma unroll
            for (int mf = 0; mf < MF; mf++) {
                uint32_t ro = (wm0 + mf * 16 + li) * 64 + coff;
                ldsm4(ah[mf], tA + ro);
            }
            uint32_t bh[NF][2];
            #pragma unroll
            for (int nf2 = 0; nf2 < NF / 2; nf2++) {
                uint32_t ro = (wn0 + nf2 * 16 + li) * 64 + coff;
                uint32_t t[4];
                ldsm4(t, tB + ro);
                bh[2 * nf2][0] = t[0]; bh[2 * nf2][1] = t[2];
                bh[2 * nf2 + 1][0] = t[1]; bh[2 * nf2 + 1][1] = t[3];
            }
            #pragma unroll
            for (int mf = 0; mf < MF; mf++)
                #pragma unroll
                for (int nf = 0; nf < NF; nf++)
                    mma16816(acc[mf][nf], ah[mf], bh[nf]);
        }
        __syncthreads();
    }

    float* st = reinterpret_cast<float*>(smem) + warp * (WM * 33);
    #pragma unroll
    for (int mf = 0; mf < MF; mf++)
        #pragma unroll
        for (int nf = 0; nf < NF; nf++)
            #pragma unroll
            for (int i = 0; i < 2; i++) {
                int r = mf * 16 + (lane >> 2) + 8 * i;
                int c = nf * 8 + 2 * (lane & 3);
                st[r * 33 + c]     = acc[mf][nf][2 * i];
                st[r * 33 + c + 1] = acc[mf][nf][2 * i + 1];
            }
    __syncwarp();
    #pragma unroll
    for (int rr = lane; rr < WM; rr += 32) {
        const int m = m0 + wm0 + rr;
        const int nbase = n0 + wn0;
        if (MODE == 1) {
            const float tm = srow[m];
            #pragma unroll
            for (int c = 0; c < WN; c += 2) {
                int n = nbase + c;
                float v0 = st[rr * 33 + c]     + tm * ucol[n]     + bias[n];
                float v1 = st[rr * 33 + c + 1] + tm * ucol[n + 1] + bias[n + 1];
                __half2 ph;
                ph.x = __float2half_rn(v0); ph.y = __float2half_rn(v1);
                *reinterpret_cast<__half2*>(Ch + (size_t)m * ldc + n) = ph;
            }
        } else {
            #pragma unroll
            for (int c4 = 0; c4 < WN; c4 += 4) {
                float4 v;
                v.x = st[rr * 33 + c4];
                v.y = st[rr * 33 + c4 + 1];
                v.z = st[rr * 33 + c4 + 2];
                v.w = st[rr * 33 + c4 + 3];
                int n = nbase + c4;
                v.x += bias[n]; v.y += bias[n + 1];
                v.z += bias[n + 2]; v.w += bias[n + 3];
                *reinterpret_cast<float4*>(C + (size_t)m * ldc + nbase + c4) = v;
            }
        }
    }
}

// ---------------- persistent fused LSTM: B resident in smem ------------------
// grid (64, 2) = 128 CTAs x 256 threads, 1 CTA/SM (152KB smem), all resident.
// B tile (W_hh rows n0..n0+63, all K=1024) loaded ONCE into smem; per step only
// the A tile (h) streams. y-group barriers (2 groups of 64 CTAs).
__global__ void __launch_bounds__(256)
lstm_persist(const __half* __restrict__ hhb,
             const __half* __restrict__ Bm,
             const float* __restrict__ xg, float* __restrict__ cstate,
             float* __restrict__ houtf,
             __half* __restrict__ hhw)
{
    constexpr int BM = 64, BN = 64, NT = 256, NF = 4;
    constexpr int ASTG = BM * 128;               // 8192 per A stage (64 cols)
    constexpr int OFF_B = 3 * ASTG;              // 24576; B 16*8192 = 131072
    // total smem = 155648

    extern __shared__ char smem[];
    const uint32_t sbase = smem_u32(smem);
    const int tid  = threadIdx.x;
    const int lane = tid & 31;
    const int warp = tid >> 5;
    const int wm0 = (warp >> 1) * 16;            // 4 m-subtiles of 16
    const int wn0 = (warp & 1) * 32;             // 2 n-subtiles of 32
    const int m0 = blockIdx.y * BM;
    const int n0 = blockIdx.x * BN;
    const int li  = lane & 15;
    const int qhb = lane >> 4;
    unsigned* ybar = &g_bar4[blockIdx.y * 32];   // 128B-separated counters

    auto dev_barrier = [&](unsigned sv) {
        __threadfence();
        __syncthreads();
        if (tid == 0) {
            atomicAdd(ybar, 1u);
            volatile unsigned* vb = ybar;
            const unsigned target = 64u * sv;
            while (*vb < target) { }
        }
        __syncthreads();
    };

    // ---- load resident B: 16 stages x 64 rows x 128B (pre-swizzled) ----
    {
        #pragma unroll
        for (int q = 0; q < 32; q++) {
            const int i = tid + q * NT;          // 0..8191
            const int s  = i >> 9;               // stage 0..15
            const int rm = i & 511;
            const int rr = rm >> 3, c = rm & 7;
            uint32_t dst = sbase + OFF_B + s * 8192 + rr * 128 + ((c ^ (rr & 7)) << 4);
            cp_async16(dst, Bm + (size_t)(n0 + rr) * H_SZ + s * 64 + c * 8);
        }
        cp_commit();
    }

    // ---- step 0: h=c=0, gates = xg row (no smem needed) ----
    {
        __half* Oh = hhw;
        const float* xgl = xg;
        #pragma unroll
        for (int qsel = 0; qsel < NF / 2; qsel++) {
            const int nb = n0 + wn0 + qsel * 16;
            const int a  = lane & 3;
            const int j  = 4 * (nb >> 4) + a;
            #pragma unroll
            for (int i = 0; i < 2; i++) {
                const int m = m0 + wm0 + (lane >> 2) + 8 * i;
                const float* xrow = xgl + (size_t)m * (L_SZ * G4);
                float2 xif = *reinterpret_cast<const float2*>(xrow + nb + 2 * a);
                float2 xgo = *reinterpret_cast<const float2*>(xrow + nb + 8 + 2 * a);
                float ig = sigf(xif.x);
                float gg = tanhf(xgo.x), og = sigf(xgo.y);
                const int gi = (m << 10) + j;
                float cv = ig * gg;
                cstate[gi] = cv;
                float hv = og * tanhf(cv);
                Oh[gi] = __float2half_rn(hv);
            }
        }
        cp_wait0();          // resident B landed
        dev_barrier(1u);     // includes __syncthreads -> B visible to all
    }

    for (int l = 1; l < L_SZ; l++) {
        const __half* Ah = hhb + (size_t)((l + 1) & 1) * (B_SZ * H_SZ);
        __half* Oh = hhw + (size_t)(l & 1) * (B_SZ * H_SZ);
        const float* xgl = xg + (size_t)l * G4;

        float acc[NF][4];
        #pragma unroll
        for (int j = 0; j < NF; j++)
            #pragma unroll
            for (int q = 0; q < 4; q++) acc[j][q] = 0.f;

        auto load_stage = [&](int kt, int s) {
            const int k0 = kt * 64;
            const uint32_t tb = sbase + s * ASTG;
            #pragma unroll
            for (int q = 0; q < 2; q++) {
                const int i = tid + q * NT;      // 0..511
                const int rr = i >> 3, c = i & 7;
                uint32_t dst = tb + rr * 128 + ((c ^ (rr & 7)) << 4);
                cp_async16(dst, Ah + (size_t)(m0 + rr) * H_SZ + k0 + c * 8);
            }
        };

        const int KT = H_SZ >> 6;   // 16
        load_stage(0, 0); cp_commit();
        load_stage(1, 1); cp_commit();

        for (int kt = 0; kt < KT; kt++) {
            const int s = kt % 3;
            if (kt + 2 < KT) load_stage(kt + 2, (kt + 2) % 3);
            cp_commit();
            cp_wait2();
            __syncthreads();

            const uint32_t tA = sbase + s * ASTG;
            const uint32_t tB = sbase + OFF_B + kt * 8192;   // resident stage kt

            #pragma unroll
            for (int kk = 0; kk < 4; kk++) {
                const int q = kk * 2 + qhb;
                const uint32_t sw = (uint32_t)((q ^ (li & 7)) << 4);
                uint32_t ah[4];
                {
                    uint32_t ro = (wm0 + li) * 128 + sw;
                    ldsm4(ah, tA + ro);
                }
                uint32_t bh[NF][2];
                #pragma unroll
                for (int nf2 = 0; nf2 < NF / 2; nf2++) {
                    uint32_t ro = (wn0 + nf2 * 16 + li) * 128 + sw;
                    uint32_t t[4];
                    ldsm4(t, tB + ro);
                    bh[2 * nf2][0] = t[0]; bh[2 * nf2][1] = t[2];
                    bh[2 * nf2 + 1][0] = t[1]; bh[2 * nf2 + 1][1] = t[3];
                }
                #pragma unroll
                for (int nf = 0; nf < NF; nf++)
                    mma16816(acc[nf], ah, bh[nf]);
            }
            __syncthreads();
        }

        // fused gate nonlinearity + state update
        #pragma unroll
        for (int qsel = 0; qsel < NF / 2; qsel++) {
            const int nb = n0 + wn0 + qsel * 16;
            const int a  = lane & 3;
            const int j  = 4 * (nb >> 4) + a;
            #pragma unroll
            for (int i = 0; i < 2; i++) {
                const int m = m0 + wm0 + (lane >> 2) + 8 * i;
                const float* xrow = xgl + (size_t)m * (L_SZ * G4);
                float2 xif = *reinterpret_cast<const float2*>(xrow + nb + 2 * a);
                float2 xgo = *reinterpret_cast<const float2*>(xrow + nb + 8 + 2 * a);
                float xi = acc[2 * qsel][2 * i]         + xif.x;
                float xf = acc[2 * qsel][2 * i + 1]     + xif.y;
                float xgv = acc[2 * qsel + 1][2 * i]    + xgo.x;
                float xo = acc[2 * qsel + 1][2 * i + 1] + xgo.y;
                float ig = sigf(xi), fg = sigf(xf);
                float gg = tanhf(xgv), og = sigf(xo);
                const int gi = (m << 10) + j;
                float cv = fg * cstate[gi] + ig * gg;
                cstate[gi] = cv;
                float hv = og * tanhf(cv);
                houtf[gi] = hv;
                Oh[gi] = __float2half_rn(hv);
            }
        }

        dev_barrier((unsigned)(l + 1));
    }
}

// ---------------- converts ---------------------------------------------------
__global__ void conv_round(const float* __restrict__ src, int C, int srcld,
                           __half* __restrict__ dst)
{
    int c16 = (blockIdx.x * blockDim.x + threadIdx.x) * 16;
    int r = blockIdx.y;
    if (c16 >= C) return;
    const float* s = src + (size_t)r * srcld + c16;
    float4 x0 = *reinterpret_cast<const float4*>(s);
    float4 x1 = *reinterpret_cast<const float4*>(s + 4);
    float4 x2 = *reinterpret_cast<const float4*>(s + 8);
    float4 x3 = *reinterpret_cast<const float4*>(s + 12);
    uint4 p0, p1;
    p0.x = pack2(x0.x, x0.y); p0.y = pack2(x0.z, x0.w);
    p0.z = pack2(x1.x, x1.y); p0.w = pack2(x1.z, x1.w);
    p1.x = pack2(x2.x, x2.y); p1.y = pack2(x2.z, x2.w);
    p1.z = pack2(x3.x, x3.y); p1.w = pack2(x3.z, x3.w);
    __half* d = dst + (size_t)r * C + c16;
    *reinterpret_cast<uint4*>(d)     = p0;
    *reinterpret_cast<uint4*>(d + 8) = p1;
}

__global__ void conv_perm_round(const float* __restrict__ src, int cols,
                                __half* __restrict__ dst)
{
    int c8 = (blockIdx.x * blockDim.x + threadIdx.x) * 8;
    int r = blockIdx.y;
    if (c8 >= cols) return;
    int gate = ((r >> 3) & 1) * 2 + (r & 1);
    int cell = 4 * (r >> 4) + ((r >> 1) & 3);
    int orig = gate * 1024 + cell;
    float4 x0 = *reinterpret_cast<const float4*>(src + (size_t)orig * cols + c8);
    float4 x1 = *reinterpret_cast<const float4*>(src + (size_t)orig * cols + c8 + 4);
    uint4 p;
    p.x = pack2(x0.x, x0.y); p.y = pack2(x0.z, x0.w);
    p.z = pack2(x1.x, x1.y); p.w = pack2(x1.z, x1.w);
    *reinterpret_cast<uint4*>(dst + (size_t)r * cols + c8) = p;
}

__global__ void prep_kernel(const float* __restrict__ Wvt,
                            const float* __restrict__ wtw,
                            const float* __restrict__ wtb,
                            const float* __restrict__ bih,
                            const float* __restrict__ bhh)
{
    int i = blockIdx.x * blockDim.x + threadIdx.x;
    if (i < 128) g_bar4[i] = 0;
    if (i < HIN) {
        const float* row = Wvt + (size_t)i * (HIN + 128) + HIN;
        float u = 0.f, ub = 0.f;
        #pragma unroll 4
        for (int j = 0; j < 128; j++) { float w = row[j]; u += w * wtw[j]; ub += w * wtb[j]; }
        g_u[i] = u; g_ub[i] = ub;
    } else if (i < HIN + G4) {
        int r = i - HIN;
        int gate = ((r >> 3) & 1) * 2 + (r & 1);
        int cell = 4 * (r >> 4) + ((r >> 1) & 3);
        g_biasp[r] = bih[gate * 1024 + cell] + bhh[gate * 1024 + cell];
    } else if (i < HIN + G4 + HIN * HIN / 8) {
        int w = i - (HIN + G4);
        int r = w >> 6;
        int c8 = (w & 63) * 8;
        float4 x0 = *reinterpret_cast<const float4*>(Wvt + (size_t)r * (HIN + 128) + c8);
        float4 x1 = *reinterpret_cast<const float4*>(Wvt + (size_t)r * (HIN + 128) + c8 + 4);
        uint4 p;
        p.x = pack2(x0.x, x0.y); p.y = pack2(x0.z, x0.w);
        p.z = pack2(x1.x, x1.y); p.w = pack2(x1.z, x1.w);
        *reinterpret_cast<uint4*>(g_wvt + (size_t)r * HIN + c8) = p;
    }
}

__global__ void reduce_conv(void)
{
    int idx = blockIdx.x * 256 + threadIdx.x;
    float s = 0.f;
    #pragma unroll
    for (int z = 0; z < KSPLIT; z++) s += g_split[(size_t)z * ML * HIN + idx];
    g_vdh[idx] = __float2half_rn(s);
}

__global__ void pred_kernel(const float* __restrict__ lw,
                            const float* __restrict__ lb,
                            float* __restrict__ out)
{
    int b = blockIdx.x, tid = threadIdx.x;
    const float* hr = g_h + (size_t)b * H_SZ;
    float s = 0.f;
    for (int k = tid; k < H_SZ; k += 128) s += hr[k] * lw[k];
    __shared__ float red[128];
    red[tid] = s; __syncthreads();
    for (int off = 64; off > 0; off >>= 1) {
        if (tid < off) red[tid] += red[tid + off];
        __syncthreads();
    }
    if (tid == 0) out[b] = red[0] + lb[0];
}

// ---------------- launch -----------------------------------------------------
#define SMEM_G1   67584                          // max(pipeline 40960, epilogue)
#define SMEM_G2   ((64 + 128) * 64 * 3)          // 36864 (BM=64 1-term)
#define SMEM_T1   67584                          // BM=128 1-term (epilogue bound)
#define SMEM_LSTM (3 * 8192 + 16 * 8192)         // 155648 (A ring + resident B)

extern "C" void kernel_launch(void* const* d_in, const int* in_sizes, int n_in,
                              void* d_out, int out_size)
{
    const float* v   = (const float*)d_in[0];
    const float* t   = (const float*)d_in[1];
    const float* Wd  = (const float*)d_in[2];
    const float* wtw = (const float*)d_in[3];
    const float* wtb = (const float*)d_in[4];
    const float* Wvt = (const float*)d_in[5];
    const float* Wih = (const float*)d_in[6];
    const float* Whh = (const float*)d_in[7];
    const float* bih = (const float*)d_in[8];
    const float* bhh = (const float*)d_in[9];
    const float* lw  = (const float*)d_in[10];
    const float* lb  = (const float*)d_in[11];
    float* out = (float*)d_out;

    __half *p_wd, *p_vdh, *p_wvt, *p_ih, *p_wih, *p_whh, *p_hh;
    float *p_split, *p_xg, *p_h, *p_c, *p_u, *p_ub, *p_biasp;
    cudaGetSymbolAddress((void**)&p_wd, g_wd);
    cudaGetSymbolAddress((void**)&p_vdh, g_vdh);
    cudaGetSymbolAddress((void**)&p_wvt, g_wvt);
    cudaGetSymbolAddress((void**)&p_ih, g_ih);
    cudaGetSymbolAddress((void**)&p_wih, g_wih); cudaGetSymbolAddress((void**)&p_whh, g_whh);
    cudaGetSymbolAddress((void**)&p_hh, g_hh);
    cudaGetSymbolAddress((void**)&p_split, g_split);
    cudaGetSymbolAddress((void**)&p_xg, g_xg);
    cudaGetSymbolAddress((void**)&p_h, g_h);     cudaGetSymbolAddress((void**)&p_c, g_c);
    cudaGetSymbolAddress((void**)&p_u, g_u);     cudaGetSymbolAddress((void**)&p_ub, g_ub);
    cudaGetSymbolAddress((void**)&p_biasp, g_biasp);

    cudaFuncSetAttribute(gemm1_fused, cudaFuncAttributeMaxDynamicSharedMemorySize, SMEM_G1);
    cudaFuncSetAttribute(mma_gemm<64, 128, 32, 32, 1>, cudaFuncAttributeMaxDynamicSharedMemorySize, SMEM_G2);
    cudaFuncSetAttribute(mma_gemm<128, 128, 64, 32, 2>, cudaFuncAttributeMaxDynamicSharedMemorySize, SMEM_T1);
    cudaFuncSetAttribute(lstm_persist, cudaFuncAttributeMaxDynamicSharedMemorySize, SMEM_LSTM);

    // 1) prep  2) W_down round  3) W_ih perm-round
    prep_kernel<<<(HIN + G4 + HIN * HIN / 8 + 255) / 256, 256>>>(Wvt, wtw, wtb, bih, bhh);
    conv_round<<<dim3((N_SZ / 16 + 255) / 256, HIN), 256>>>(Wd, N_SZ, N_SZ, p_wd);
    conv_perm_round<<<dim3(1, G4), 256>>>(Wih, HIN, p_wih);

    // 4) GEMM1 (LDG-reg convert, 1-term, split-K=4)
    gemm1_fused<<<dim3(HIN / 128, ML / 128, KSPLIT), 256, SMEM_G1>>>(
        v, N_SZ, p_wd, N_SZ, p_split, HIN, (size_t)ML * HIN);

    // 5) reduce partials -> vd fp16
    reduce_conv<<<(ML * HIN) / 256, 256>>>();

    // 6) GEMM2 (1-term, 64x128 tiles -> 128 CTAs)
    mma_gemm<64, 128, 32, 32, 1><<<dim3(HIN / 128, ML / 64), 256, SMEM_G2>>>(
        p_vdh, HIN, p_wvt, HIN, HIN,
        nullptr, HIN, p_ub, t, p_u, p_ih);

    // 7) GEMM3 (1-term): xg = inputs_fp16 @ Wih_perm^T + bias_perm
    mma_gemm<128, 128, 64, 32, 2><<<dim3(G4 / 128, ML / 128), 256, SMEM_T1>>>(
        p_ih, HIN, p_wih, HIN, HIN,
        p_xg, G4, p_biasp, nullptr, nullptr, nullptr);

    // 8) W_hh perm-round  9) persistent LSTM (resident B, 128 CTAs)
    conv_perm_round<<<dim3(1, G4), 256>>>(Whh, H_SZ, p_whh);
    lstm_persist<<<dim3(G4 / 64, B_SZ / 64), 256, SMEM_LSTM>>>(
        p_hh, p_whh, p_xg, p_c, p_h, p_hh);

    // 10) pred
    pred_kernel<<<B_SZ, 128>>>(lw, lb, out);
}